// round 14
// baseline (speedup 1.0000x reference)
#include <cuda_runtime.h>
#include <cuda_fp16.h>
#include <cstdint>

#define NN 100000
#define FDIM 128
#define EMAX 1700032
#define NBMAX 512

typedef unsigned long long ull;

// Scratch (device globals — allocation-free per harness rules)
__device__ __half g_h16a[NN * FDIM];  // layer-1 fp16 messages
__device__ __half g_h16b[NN * FDIM];  // layer-2 fp16 messages (double buffer)
__device__ float g_out[NN * FDIM];    // aggregated + relu(·+bias) output (fp32)
__device__ float g_asrcA[NN * 4];
__device__ float g_adstA[NN * 4];
__device__ float g_asrcB[NN * 4];     // layer-2 logits (double buffer)
__device__ float g_adstB[NN * 4];
__device__ float g_wpad[FDIM * 64];   // Wc zero-padded to 128x64
__device__ float g_w1tf[FDIM * FDIM]; // W1^T, tf32-rounded, k pair-interleaved
__device__ float g_w2tf[FDIM * FDIM]; // W2^T, tf32-rounded, k pair-interleaved
__device__ int   g_rowptr[NN + 1];
__device__ int   g_wcur[NN];
__device__ int   g_csrc[EMAX];
__device__ int   g_bsum[NBMAX];

// ---------------------------------------------------------------------------
// packed f32x2 helpers (classifier GEMM)
// ---------------------------------------------------------------------------
#define PACK2(out, lo, hi) \
    asm("mov.b64 %0, {%1, %2};" : "=l"(out) : "f"(lo), "f"(hi))
#define UNPK2(lo, hi, in) \
    asm("mov.b64 {%0, %1}, %2;" : "=f"(lo), "=f"(hi) : "l"(in))
#define FMA2(d, a, b, c) \
    asm("fma.rn.f32x2 %0, %1, %2, %3;" : "=l"(d) : "l"(a), "l"(b), "l"(c))

__device__ __forceinline__ uint32_t f2tf(float f) {
    uint32_t r;
    asm("cvt.rna.tf32.f32 %0, %1;" : "=r"(r) : "f"(f));
    return r;
}
#define MMA_TF32(c, a, b) \
    asm volatile("mma.sync.aligned.m16n8k8.row.col.f32.tf32.tf32.f32 " \
        "{%0,%1,%2,%3}, {%4,%5,%6,%7}, {%8,%9}, {%0,%1,%2,%3};" \
        : "+f"((c)[0]), "+f"((c)[1]), "+f"((c)[2]), "+f"((c)[3]) \
        : "r"((a)[0]), "r"((a)[1]), "r"((a)[2]), "r"((a)[3]), \
          "r"((b)[0]), "r"((b)[1]))

__device__ __forceinline__ uint32_t s2u(const void* p) {
    uint32_t a;
    asm("{ .reg .u64 t; cvta.to.shared.u64 t, %1; cvt.u32.u64 %0, t; }"
        : "=r"(a) : "l"(p));
    return a;
}
__device__ __forceinline__ void cpa16(uint32_t dst, const void* src, bool pred) {
    int sz = pred ? 16 : 0;   // src-size 0 -> zero-fill, no read
    asm volatile("cp.async.ca.shared.global [%0], [%1], 16, %2;"
                 :: "r"(dst), "l"(src), "r"(sz));
}
#define CPA_COMMIT() asm volatile("cp.async.commit_group;" ::: "memory")
#define CPA_WAIT(n)  asm volatile("cp.async.wait_group %0;" :: "n"(n) : "memory")

// rna-to-tf32 via bit trick: fp32 is sign-magnitude, so adding 0x1000 and
// letting the tensor core truncate the low 13 bits == cvt.rna.tf32.f32.
#define RNA13(u) ((u) + 0x1000u)

// dynamic smem layout (floats)
#define OFF_A0   0
#define OFF_A1   4608        // 128*36
#define OFF_W0   9216
#define OFF_W1   14336       // + 128*40
#define OFF_ATTS 19456
#define OFF_ATTD 19584
#define SMEM_FLOATS 19712    // 78848 bytes

// ---------------------------------------------------------------------------
// TF32 tensor GEMM, cp.async double-buffered, fused attention epilogue.
// 512 threads, 16 warps (4M x 4N), warp tile 32x32. W transposed +
// k-pair-interleaved -> B frags are LDS.64, stride 40 conflict-free.
// ---------------------------------------------------------------------------
__global__ void __launch_bounds__(512) mma_gemm_k(
    const float* __restrict__ A, const float* __restrict__ WtfT,
    __half* __restrict__ h16,
    float* __restrict__ a_s, float* __restrict__ a_d,
    const float* __restrict__ att_s, const float* __restrict__ att_d, int M)
{
    extern __shared__ float smem[];
    const uint32_t sb = s2u(smem);
    const int tid = threadIdx.x;
    const int lane = tid & 31;
    const int w = tid >> 5;
    const int wm = (w & 3) * 32;
    const int wn = (w >> 2) * 32;      // one head per warp
    const int r0 = blockIdx.x * 128;

    if (tid < 128) {
        smem[OFF_ATTS + tid] = att_s[tid];
        smem[OFF_ATTD + tid] = att_d[tid];
    }

    auto load_slab = [&](int kb, int buf) {
        const uint32_t aB = sb + (buf ? OFF_A1 : OFF_A0) * 4;
        const uint32_t wB = sb + (buf ? OFF_W1 : OFF_W0) * 4;
#pragma unroll
        for (int i = 0; i < 2; i++) {
            int idx = tid + i * 512;
            int row = idx >> 3, cg = idx & 7;
            int g = r0 + row;
            bool ok = g < M;
            cpa16(aB + (row * 36 + cg * 4) * 4,
                  A + (size_t)(ok ? g : 0) * 128 + kb * 32 + cg * 4, ok);
        }
#pragma unroll
        for (int i = 0; i < 2; i++) {
            int idx = tid + i * 512;
            int n = idx >> 3, cg = idx & 7;
            cpa16(wB + (n * 40 + cg * 4) * 4,
                  WtfT + (size_t)n * 128 + kb * 32 + cg * 4, true);
        }
    };

    float acc[2][4][4];
#pragma unroll
    for (int tm = 0; tm < 2; tm++)
#pragma unroll
        for (int tn = 0; tn < 4; tn++)
#pragma unroll
            for (int i = 0; i < 4; i++) acc[tm][tn][i] = 0.f;

    load_slab(0, 0);
    CPA_COMMIT();

#pragma unroll
    for (int kb = 0; kb < 4; kb++) {
        const int buf = kb & 1;
        if (kb < 3) {
            load_slab(kb + 1, buf ^ 1);
            CPA_COMMIT();
            CPA_WAIT(1);
        } else {
            CPA_WAIT(0);
        }
        __syncthreads();

        const float* sA = smem + (buf ? OFF_A1 : OFF_A0);
        const float* sW = smem + (buf ? OFF_W1 : OFF_W0);

#pragma unroll
        for (int k8 = 0; k8 < 4; k8++) {
            const int kq = k8 * 8 + (lane & 3);
            const int rb = wm + (lane >> 2);
            const int nb = wn + (lane >> 2);
            uint32_t a[2][4], b[4][2];
#pragma unroll
            for (int tm = 0; tm < 2; tm++) {
                a[tm][0] = RNA13(__float_as_uint(sA[(rb + tm * 16 + 0) * 36 + kq]));
                a[tm][1] = RNA13(__float_as_uint(sA[(rb + tm * 16 + 8) * 36 + kq]));
                a[tm][2] = RNA13(__float_as_uint(sA[(rb + tm * 16 + 0) * 36 + kq + 4]));
                a[tm][3] = RNA13(__float_as_uint(sA[(rb + tm * 16 + 8) * 36 + kq + 4]));
            }
#pragma unroll
            for (int tn = 0; tn < 4; tn++) {
                float2 bp = *(const float2*)&sW[(nb + tn * 8) * 40 +
                                                k8 * 8 + 2 * (lane & 3)];
                b[tn][0] = __float_as_uint(bp.x);
                b[tn][1] = __float_as_uint(bp.y);
            }
#pragma unroll
            for (int tm = 0; tm < 2; tm++)
#pragma unroll
                for (int tn = 0; tn < 4; tn++)
                    MMA_TF32(acc[tm][tn], a[tm], b[tn]);
        }
        __syncthreads();
    }

    // ---- fused epilogue: fp16 store + attn logits (one head per warp) ----
    const float* satt_s = smem + OFF_ATTS;
    const float* satt_d = smem + OFF_ATTD;
    const int head = wn >> 5;
#pragma unroll
    for (int tm = 0; tm < 2; tm++)
#pragma unroll
        for (int h2 = 0; h2 < 2; h2++) {
            int gr = r0 + wm + tm * 16 + (lane >> 2) + 8 * h2;
            if (gr < M) {
#pragma unroll
                for (int tn = 0; tn < 4; tn++) {
                    __half2 hh = __floats2half2_rn(acc[tm][tn][2 * h2],
                                                   acc[tm][tn][2 * h2 + 1]);
                    *(uint32_t*)(h16 + (size_t)gr * 128 + wn + tn * 8 +
                                 (lane & 3) * 2) = *(uint32_t*)&hh;
                }
            }
            float s0 = 0.f, d0 = 0.f;
#pragma unroll
            for (int tn = 0; tn < 4; tn++) {
                int col = wn + tn * 8 + (lane & 3) * 2;
                float x0 = acc[tm][tn][2 * h2], x1 = acc[tm][tn][2 * h2 + 1];
                s0 += x0 * satt_s[col] + x1 * satt_s[col + 1];
                d0 += x0 * satt_d[col] + x1 * satt_d[col + 1];
            }
#pragma unroll
            for (int off = 1; off <= 2; off <<= 1) {
                s0 += __shfl_xor_sync(0xFFFFFFFF, s0, off);
                d0 += __shfl_xor_sync(0xFFFFFFFF, d0, off);
            }
            if ((lane & 3) == 0 && gr < M) {
                a_s[(size_t)gr * 4 + head] = s0;
                a_d[(size_t)gr * 4 + head] = d0;
            }
        }
}

// ---------------------------------------------------------------------------
// Classifier GEMM (exact fp32 FFMA2): C[M,40] = A @ Wpad[128,64] + b_out
// ---------------------------------------------------------------------------
__global__ void __launch_bounds__(256) gemm_cls_k(
    const float* __restrict__ A, const float* __restrict__ W,
    float* __restrict__ C, const float* __restrict__ bias_out, int M)
{
    __shared__ float sAT[32][130];
    __shared__ float sW[32][64];

    const int tid = threadIdx.x;
    const int tx = tid & 15;
    const int ty = tid >> 4;
    const int r0 = blockIdx.x * 128;

    ull acc[4][4];
#pragma unroll
    for (int p = 0; p < 4; p++)
#pragma unroll
        for (int c = 0; c < 4; c++) acc[p][c] = 0ull;

    for (int k0 = 0; k0 < 128; k0 += 32) {
#pragma unroll
        for (int i = 0; i < 4; i++) {
            int f = tid + i * 256;
            int row = f >> 3;
            int cg = f & 7;
            int grow = r0 + row;
            float4 v = make_float4(0.f, 0.f, 0.f, 0.f);
            if (grow < M)
                v = *(const float4*)(A + (size_t)grow * 128 + k0 + cg * 4);
            sAT[cg * 4 + 0][row] = v.x;
            sAT[cg * 4 + 1][row] = v.y;
            sAT[cg * 4 + 2][row] = v.z;
            sAT[cg * 4 + 3][row] = v.w;
        }
#pragma unroll
        for (int i = 0; i < 2; i++) {
            int f = tid + i * 256;
            int row = f >> 4;
            int cg = f & 15;
            *(float4*)&sW[row][cg * 4] =
                *(const float4*)(W + (size_t)(k0 + row) * 64 + cg * 4);
        }
        __syncthreads();

#pragma unroll 8
        for (int k = 0; k < 32; k++) {
            float4 w = *(float4*)&sW[k][tx * 4];
            ull b0, b1, b2, b3;
            PACK2(b0, w.x, w.x);
            PACK2(b1, w.y, w.y);
            PACK2(b2, w.z, w.z);
            PACK2(b3, w.w, w.w);
            const ull* ap = (const ull*)&sAT[k][ty * 8];
            ull a0 = ap[0], a1 = ap[1], a2 = ap[2], a3 = ap[3];
            FMA2(acc[0][0], a0, b0, acc[0][0]);
            FMA2(acc[0][1], a0, b1, acc[0][1]);
            FMA2(acc[0][2], a0, b2, acc[0][2]);
            FMA2(acc[0][3], a0, b3, acc[0][3]);
            FMA2(acc[1][0], a1, b0, acc[1][0]);
            FMA2(acc[1][1], a1, b1, acc[1][1]);
            FMA2(acc[1][2], a1, b2, acc[1][2]);
            FMA2(acc[1][3], a1, b3, acc[1][3]);
            FMA2(acc[2][0], a2, b0, acc[2][0]);
            FMA2(acc[2][1], a2, b1, acc[2][1]);
            FMA2(acc[2][2], a2, b2, acc[2][2]);
            FMA2(acc[2][3], a2, b3, acc[2][3]);
            FMA2(acc[3][0], a3, b0, acc[3][0]);
            FMA2(acc[3][1], a3, b1, acc[3][1]);
            FMA2(acc[3][2], a3, b2, acc[3][2]);
            FMA2(acc[3][3], a3, b3, acc[3][3]);
        }
        __syncthreads();
    }

    int col = tx * 4;
    if (col < 40) {
        float4 bo = *(const float4*)(bias_out + col);
#pragma unroll
        for (int p = 0; p < 4; p++) {
            float4 v0, v1;
            UNPK2(v0.x, v1.x, acc[p][0]);
            UNPK2(v0.y, v1.y, acc[p][1]);
            UNPK2(v0.z, v1.z, acc[p][2]);
            UNPK2(v0.w, v1.w, acc[p][3]);
            int gr0 = r0 + ty * 8 + 2 * p;
            if (gr0 < M) {
                v0.x += bo.x; v0.y += bo.y; v0.z += bo.z; v0.w += bo.w;
                *(float4*)(C + (size_t)gr0 * 40 + col) = v0;
            }
            if (gr0 + 1 < M) {
                v1.x += bo.x; v1.y += bo.y; v1.z += bo.z; v1.w += bo.w;
                *(float4*)(C + (size_t)(gr0 + 1) * 40 + col) = v1;
            }
        }
    }
}

// ---------------------------------------------------------------------------
// prep: pad Wc, build W1^T/W2^T tf32-rounded k-pair-interleaved, seed counts
// ---------------------------------------------------------------------------
__global__ void prep_k(const float* __restrict__ wc, float* __restrict__ wpad,
                       const float* __restrict__ w1, float* __restrict__ w1tf,
                       const float* __restrict__ w2, float* __restrict__ w2tf,
                       int* __restrict__ cnt, int N)
{
    int t = blockIdx.x * blockDim.x + threadIdx.x;
    if (t < 128 * 64) {
        int r = t >> 6, c = t & 63;
        wpad[t] = (c < 40) ? wc[r * 40 + c] : 0.f;
    }
    if (t < 128 * 128) {
        int n = t >> 7, j = t & 127;
        int k = ((j >> 3) << 3) + ((j >> 1) & 3) + ((j & 1) << 2);
        w1tf[t] = __uint_as_float(f2tf(w1[k * 128 + n]));
        w2tf[t] = __uint_as_float(f2tf(w2[k * 128 + n]));
    }
    if (t < N) cnt[t] = 1;
}

// ---------------------------------------------------------------------------
// CSR build: count, 3-kernel scan, scatter fill
// ---------------------------------------------------------------------------
__global__ void count_k(const int* __restrict__ ei, int E, int* __restrict__ cnt)
{
    int i = blockIdx.x * blockDim.x + threadIdx.x;
    if (i < E) atomicAdd(cnt + __ldg(ei + E + i), 1);
}

__global__ void blocksum_k(const int* __restrict__ cnt, int* __restrict__ bsum, int N)
{
    __shared__ int s[256];
    int i = blockIdx.x * 256 + threadIdx.x;
    s[threadIdx.x] = (i < N) ? cnt[i] : 0;
    __syncthreads();
#pragma unroll
    for (int st = 128; st > 0; st >>= 1) {
        if (threadIdx.x < st) s[threadIdx.x] += s[threadIdx.x + st];
        __syncthreads();
    }
    if (threadIdx.x == 0) bsum[blockIdx.x] = s[0];
}

__global__ void scan_bsums_k(int* __restrict__ bsum, int NB)
{
    __shared__ int s[NBMAX];
    int t = threadIdx.x;
    int x = (t < NB) ? bsum[t] : 0;
    s[t] = x;
    __syncthreads();
#pragma unroll
    for (int off = 1; off < NBMAX; off <<= 1) {
        int v = (t >= off) ? s[t - off] : 0;
        __syncthreads();
        s[t] += v;
        __syncthreads();
    }
    bsum[t < NBMAX ? t : 0] = s[t] - x;
}

__global__ void scan_final_k(const int* __restrict__ cnt,
                             const int* __restrict__ boff,
                             int* __restrict__ rowptr,
                             int* __restrict__ wcur, int N)
{
    __shared__ int s[256];
    int t = threadIdx.x;
    int i = blockIdx.x * 256 + t;
    int x = (i < N) ? cnt[i] : 0;
    s[t] = x;
    __syncthreads();
#pragma unroll
    for (int off = 1; off < 256; off <<= 1) {
        int v = (t >= off) ? s[t - off] : 0;
        __syncthreads();
        s[t] += v;
        __syncthreads();
    }
    int excl = s[t] - x + boff[blockIdx.x];
    if (i < N) {
        rowptr[i] = excl;
        wcur[i] = excl;
        if (i == N - 1) rowptr[N] = excl + x;
    }
}

__global__ void fill_k(const int* __restrict__ ei, int E, int N,
                       int* __restrict__ wcur, int* __restrict__ csrc)
{
    int t = blockIdx.x * blockDim.x + threadIdx.x;
    int T = E + N;
    if (t >= T) return;
    int s, d;
    if (t < E) { s = __ldg(ei + t); d = __ldg(ei + E + t); }
    else       { s = t - E; d = s; }
    int pos = atomicAdd(wcur + d, 1);
    csrc[pos] = s;
}

// ---------------------------------------------------------------------------
// Aggregation: warp per dst node; two half-warps, 1-deep prefetch each.
// Epilogue applies relu(x*inv + bias). Works on a node-range via offset ptrs.
// ---------------------------------------------------------------------------
__global__ void __launch_bounds__(256) agg_k(
    const int* __restrict__ rowptr, const int* __restrict__ csrc,
    const __half* __restrict__ h16,
    const float* __restrict__ a_s, const float* __restrict__ a_d,
    const float* __restrict__ bias, float* __restrict__ out, int N)
{
    int d = (blockIdx.x * blockDim.x + threadIdx.x) >> 5;
    int lane = threadIdx.x & 31;
    if (d >= N) return;

    const int half = lane >> 4;
    const int sl = lane & 15;
    const int head = sl >> 2;
    int beg = __ldg(rowptr + d);
    int end = __ldg(rowptr + d + 1);
    float ed = __ldg(a_d + 4 * (size_t)d + head);

    float acc[8];
#pragma unroll
    for (int j = 0; j < 8; j++) acc[j] = 0.f;
    float den = 0.f;

    int e = beg + half;
    if (e < end) {
        int s = __ldg(csrc + e);
        float es = __ldg(a_s + 4 * (size_t)s + head);
        uint4 pk = *(const uint4*)(h16 + (size_t)s * 128 + sl * 8);
        for (;;) {
            int e2 = e + 2;
            bool more = e2 < end;
            float esN = 0.f;
            uint4 pkN = make_uint4(0, 0, 0, 0);
            if (more) {
                int sn = __ldg(csrc + e2);
                esN = __ldg(a_s + 4 * (size_t)sn + head);
                pkN = *(const uint4*)(h16 + (size_t)sn * 128 + sl * 8);
            }
            float t = es + ed;
            t = (t > 0.f) ? t : 0.2f * t;
            float p = __expf(t);
            den += p;
            const __half2* hp = (const __half2*)&pk;
#pragma unroll
            for (int j = 0; j < 4; j++) {
                float2 f = __half22float2(hp[j]);
                acc[2 * j] = fmaf(p, f.x, acc[2 * j]);
                acc[2 * j + 1] = fmaf(p, f.y, acc[2 * j + 1]);
            }
            if (!more) break;
            e = e2; es = esN; pk = pkN;
        }
    }

#pragma unroll
    for (int j = 0; j < 8; j++)
        acc[j] += __shfl_down_sync(0xFFFFFFFF, acc[j], 16);
    den += __shfl_down_sync(0xFFFFFFFF, den, 16);

    if (half == 0) {
        float inv = 1.0f / (den + 1e-16f);
        float4 b0 = *(const float4*)(bias + sl * 8);
        float4 b1 = *(const float4*)(bias + sl * 8 + 4);
        float4 v0 = make_float4(fmaxf(fmaf(acc[0], inv, b0.x), 0.f),
                                fmaxf(fmaf(acc[1], inv, b0.y), 0.f),
                                fmaxf(fmaf(acc[2], inv, b0.z), 0.f),
                                fmaxf(fmaf(acc[3], inv, b0.w), 0.f));
        float4 v1 = make_float4(fmaxf(fmaf(acc[4], inv, b1.x), 0.f),
                                fmaxf(fmaf(acc[5], inv, b1.y), 0.f),
                                fmaxf(fmaf(acc[6], inv, b1.z), 0.f),
                                fmaxf(fmaf(acc[7], inv, b1.w), 0.f));
        float4* o = (float4*)(out + (size_t)d * 128 + sl * 8);
        o[0] = v0;
        o[1] = v1;
    }
}

// ---------------------------------------------------------------------------
extern "C" void kernel_launch(void* const* d_in, const int* in_sizes, int n_in,
                              void* d_out, int out_size)
{
    const float* x   = (const float*)d_in[0];
    const int*   ei  = (const int*)  d_in[1];
    const float* W1  = (const float*)d_in[2];
    const float* as1 = (const float*)d_in[3];
    const float* ad1 = (const float*)d_in[4];
    const float* b1  = (const float*)d_in[5];
    const float* W2  = (const float*)d_in[6];
    const float* as2 = (const float*)d_in[7];
    const float* ad2 = (const float*)d_in[8];
    const float* b2  = (const float*)d_in[9];
    const float* Wc  = (const float*)d_in[10];
    const float* bc  = (const float*)d_in[11];
    float* out = (float*)d_out;

    const int N = in_sizes[0] / 128;
    const int E = in_sizes[1] / 2;

    __half *h16a, *h16b;
    float *obuf, *asbA, *adbA, *asbB, *adbB, *wpad, *w1tf, *w2tf;
    int *rowptr, *wcur, *csrc, *bsum;
    cudaGetSymbolAddress((void**)&h16a,   g_h16a);
    cudaGetSymbolAddress((void**)&h16b,   g_h16b);
    cudaGetSymbolAddress((void**)&obuf,   g_out);
    cudaGetSymbolAddress((void**)&asbA,   g_asrcA);
    cudaGetSymbolAddress((void**)&adbA,   g_adstA);
    cudaGetSymbolAddress((void**)&asbB,   g_asrcB);
    cudaGetSymbolAddress((void**)&adbB,   g_adstB);
    cudaGetSymbolAddress((void**)&wpad,   g_wpad);
    cudaGetSymbolAddress((void**)&w1tf,   g_w1tf);
    cudaGetSymbolAddress((void**)&w2tf,   g_w2tf);
    cudaGetSymbolAddress((void**)&rowptr, g_rowptr);
    cudaGetSymbolAddress((void**)&wcur,   g_wcur);
    cudaGetSymbolAddress((void**)&csrc,   g_csrc);
    cudaGetSymbolAddress((void**)&bsum,   g_bsum);

    // one-time host-side init (no device allocations)
    static cudaStream_t s2 = nullptr;
    static cudaEvent_t evF, evCSR, evA0, evA1, evA2, evA3;
    if (!s2) {
        cudaStreamCreateWithFlags(&s2, cudaStreamNonBlocking);
        cudaEventCreateWithFlags(&evF,   cudaEventDisableTiming);
        cudaEventCreateWithFlags(&evCSR, cudaEventDisableTiming);
        cudaEventCreateWithFlags(&evA0,  cudaEventDisableTiming);
        cudaEventCreateWithFlags(&evA1,  cudaEventDisableTiming);
        cudaEventCreateWithFlags(&evA2,  cudaEventDisableTiming);
        cudaEventCreateWithFlags(&evA3,  cudaEventDisableTiming);
        cudaFuncSetAttribute(mma_gemm_k,
                             cudaFuncAttributeMaxDynamicSharedMemorySize,
                             SMEM_FLOATS * 4);
    }

    // chunk split (tile-aligned -> bit-identical results)
    const int NH0 = ((N / 2 + 127) / 128) * 128;   // 50048 for N=100000
    const int NH1 = N - NH0;

    const dim3 gMma((N + 127) / 128);
    const dim3 gMmaH0((NH0 + 127) / 128), gMmaH1((NH1 + 127) / 128);
    const dim3 gClsH0((NH0 + 127) / 128), gClsH1((NH1 + 127) / 128);
    const int  NB = (N + 255) / 256;
    const int  T = E + N;
    const int  gAggH0 = (NH0 + 7) / 8, gAggH1 = (NH1 + 7) / 8;
    const int  smb = SMEM_FLOATS * 4;

    // ---- phase 0: prep (main), fork CSR chain to s2, GEMM1 on main ----
    prep_k<<<NB, 256>>>(Wc, wpad, W1, w1tf, W2, w2tf, wcur, N);
    cudaEventRecord(evF, 0);
    cudaStreamWaitEvent(s2, evF, 0);

    count_k<<<(E + 255) / 256, 256, 0, s2>>>(ei, E, wcur);
    blocksum_k<<<NB, 256, 0, s2>>>(wcur, bsum, N);
    mma_gemm_k<<<gMma, 512, smb>>>(x, w1tf, h16a, asbA, adbA, as1, ad1, N);
    scan_bsums_k<<<1, NBMAX, 0, s2>>>(bsum, NB);
    scan_final_k<<<NB, 256, 0, s2>>>(wcur, bsum, rowptr, wcur, N);
    fill_k<<<(T + 255) / 256, 256, 0, s2>>>(ei, E, N, wcur, csrc);
    cudaEventRecord(evCSR, s2);
    cudaStreamWaitEvent(0, evCSR, 0);

    // ---- phase 1: agg1 (reads h16a/asbA) staggered with GEMM2 (writes
    //      h16b/asbB — disjoint buffers, no WAR race) ----
    agg_k<<<gAggH0, 256>>>(rowptr, csrc, h16a, asbA, adbA, b1, obuf, NH0);
    cudaEventRecord(evA0, 0);
    cudaStreamWaitEvent(s2, evA0, 0);
    // s2: second agg1 chunk (overlaps GEMM2 chunk 0 on main)
    agg_k<<<gAggH1, 256, 0, s2>>>(rowptr + NH0, csrc, h16a, asbA,
                                  adbA + 4 * (size_t)NH0, b1,
                                  obuf + (size_t)NH0 * 128, NH1);
    cudaEventRecord(evA1, s2);
    // main: GEMM2 chunk 0 (reads obuf[0,NH0), writes h16b/asbB[0,NH0))
    mma_gemm_k<<<gMmaH0, 512, smb>>>(obuf, w2tf, h16b, asbB, adbB,
                                     as2, ad2, NH0);
    cudaStreamWaitEvent(0, evA1, 0);
    // main: GEMM2 chunk 1
    mma_gemm_k<<<gMmaH1, 512, smb>>>(obuf + (size_t)NH0 * 128, w2tf,
                                     h16b + (size_t)NH0 * 128,
                                     asbB + 4 * (size_t)NH0,
                                     adbB + 4 * (size_t)NH0, as2, ad2, NH1);

    // ---- phase 2: agg2 (reads h16b/asbB, writes obuf) staggered with
    //      classifier (reads obuf chunk 0 — disjoint rows) ----
    agg_k<<<gAggH0, 256>>>(rowptr, csrc, h16b, asbB, adbB, b2, obuf, NH0);
    cudaEventRecord(evA2, 0);
    cudaStreamWaitEvent(s2, evA2, 0);
    agg_k<<<gAggH1, 256, 0, s2>>>(rowptr + NH0, csrc, h16b, asbB,
                                  adbB + 4 * (size_t)NH0, b2,
                                  obuf + (size_t)NH0 * 128, NH1);
    cudaEventRecord(evA3, s2);
    gemm_cls_k<<<gClsH0, 256>>>(obuf, wpad, out, bc, NH0);
    cudaStreamWaitEvent(0, evA3, 0);
    gemm_cls_k<<<gClsH1, 256>>>(obuf + (size_t)NH0 * 128, wpad,
                                out + (size_t)NH0 * 40, bc, NH1);
}

// round 15
// speedup vs baseline: 1.0157x; 1.0157x over previous
#include <cuda_runtime.h>
#include <cuda_fp16.h>
#include <cstdint>

#define NN 100000
#define FDIM 128
#define EMAX 1700032
#define NBMAX 512

typedef unsigned long long ull;

// Scratch (device globals — allocation-free per harness rules)
__device__ __half g_h16a[NN * FDIM];  // layer-1 fp16 messages
__device__ __half g_h16b[NN * FDIM];  // layer-2 fp16 messages (double buffer)
__device__ float g_out[NN * FDIM];    // aggregated + relu(·+bias) output (fp32)
__device__ float g_asrcA[NN * 4];
__device__ float g_adstA[NN * 4];
__device__ float g_asrcB[NN * 4];     // layer-2 logits (double buffer)
__device__ float g_adstB[NN * 4];
__device__ float g_wpad[FDIM * 64];   // Wc zero-padded to 128x64
__device__ float g_w1tf[FDIM * FDIM]; // W1^T, tf32-rounded, k pair-interleaved
__device__ float g_w2tf[FDIM * FDIM]; // W2^T, tf32-rounded, k pair-interleaved
__device__ int   g_rowptr[NN + 1];
__device__ int   g_wcur[NN];
__device__ int   g_csrc[EMAX];
__device__ int   g_bsum[NBMAX];

// ---------------------------------------------------------------------------
// packed f32x2 helpers (classifier GEMM)
// ---------------------------------------------------------------------------
#define PACK2(out, lo, hi) \
    asm("mov.b64 %0, {%1, %2};" : "=l"(out) : "f"(lo), "f"(hi))
#define UNPK2(lo, hi, in) \
    asm("mov.b64 {%0, %1}, %2;" : "=f"(lo), "=f"(hi) : "l"(in))
#define FMA2(d, a, b, c) \
    asm("fma.rn.f32x2 %0, %1, %2, %3;" : "=l"(d) : "l"(a), "l"(b), "l"(c))

__device__ __forceinline__ uint32_t f2tf(float f) {
    uint32_t r;
    asm("cvt.rna.tf32.f32 %0, %1;" : "=r"(r) : "f"(f));
    return r;
}
#define MMA_TF32(c, a, b) \
    asm volatile("mma.sync.aligned.m16n8k8.row.col.f32.tf32.tf32.f32 " \
        "{%0,%1,%2,%3}, {%4,%5,%6,%7}, {%8,%9}, {%0,%1,%2,%3};" \
        : "+f"((c)[0]), "+f"((c)[1]), "+f"((c)[2]), "+f"((c)[3]) \
        : "r"((a)[0]), "r"((a)[1]), "r"((a)[2]), "r"((a)[3]), \
          "r"((b)[0]), "r"((b)[1]))

__device__ __forceinline__ uint32_t s2u(const void* p) {
    uint32_t a;
    asm("{ .reg .u64 t; cvta.to.shared.u64 t, %1; cvt.u32.u64 %0, t; }"
        : "=r"(a) : "l"(p));
    return a;
}
__device__ __forceinline__ void cpa16(uint32_t dst, const void* src, bool pred) {
    int sz = pred ? 16 : 0;   // src-size 0 -> zero-fill, no read
    asm volatile("cp.async.ca.shared.global [%0], [%1], 16, %2;"
                 :: "r"(dst), "l"(src), "r"(sz));
}
#define CPA_COMMIT() asm volatile("cp.async.commit_group;" ::: "memory")
#define CPA_WAIT(n)  asm volatile("cp.async.wait_group %0;" :: "n"(n) : "memory")

// rna-to-tf32 via bit trick: fp32 is sign-magnitude, so adding 0x1000 and
// letting the tensor core truncate the low 13 bits == cvt.rna.tf32.f32.
#define RNA13(u) ((u) + 0x1000u)

// dynamic smem layout (floats)
#define OFF_A0   0
#define OFF_A1   4608        // 128*36
#define OFF_W0   9216
#define OFF_W1   14336       // + 128*40
#define OFF_ATTS 19456
#define OFF_ATTD 19584
#define SMEM_FLOATS 19712    // 78848 bytes

// ---------------------------------------------------------------------------
// TF32 tensor GEMM, cp.async double-buffered, fused attention epilogue.
// 512 threads, 16 warps (4M x 4N), warp tile 32x32. W transposed +
// k-pair-interleaved -> B frags are LDS.64, stride 40 conflict-free.
// ---------------------------------------------------------------------------
__global__ void __launch_bounds__(512) mma_gemm_k(
    const float* __restrict__ A, const float* __restrict__ WtfT,
    __half* __restrict__ h16,
    float* __restrict__ a_s, float* __restrict__ a_d,
    const float* __restrict__ att_s, const float* __restrict__ att_d, int M)
{
    extern __shared__ float smem[];
    const uint32_t sb = s2u(smem);
    const int tid = threadIdx.x;
    const int lane = tid & 31;
    const int w = tid >> 5;
    const int wm = (w & 3) * 32;
    const int wn = (w >> 2) * 32;      // one head per warp
    const int r0 = blockIdx.x * 128;

    if (tid < 128) {
        smem[OFF_ATTS + tid] = att_s[tid];
        smem[OFF_ATTD + tid] = att_d[tid];
    }

    auto load_slab = [&](int kb, int buf) {
        const uint32_t aB = sb + (buf ? OFF_A1 : OFF_A0) * 4;
        const uint32_t wB = sb + (buf ? OFF_W1 : OFF_W0) * 4;
#pragma unroll
        for (int i = 0; i < 2; i++) {
            int idx = tid + i * 512;
            int row = idx >> 3, cg = idx & 7;
            int g = r0 + row;
            bool ok = g < M;
            cpa16(aB + (row * 36 + cg * 4) * 4,
                  A + (size_t)(ok ? g : 0) * 128 + kb * 32 + cg * 4, ok);
        }
#pragma unroll
        for (int i = 0; i < 2; i++) {
            int idx = tid + i * 512;
            int n = idx >> 3, cg = idx & 7;
            cpa16(wB + (n * 40 + cg * 4) * 4,
                  WtfT + (size_t)n * 128 + kb * 32 + cg * 4, true);
        }
    };

    float acc[2][4][4];
#pragma unroll
    for (int tm = 0; tm < 2; tm++)
#pragma unroll
        for (int tn = 0; tn < 4; tn++)
#pragma unroll
            for (int i = 0; i < 4; i++) acc[tm][tn][i] = 0.f;

    load_slab(0, 0);
    CPA_COMMIT();

#pragma unroll
    for (int kb = 0; kb < 4; kb++) {
        const int buf = kb & 1;
        if (kb < 3) {
            load_slab(kb + 1, buf ^ 1);
            CPA_COMMIT();
            CPA_WAIT(1);
        } else {
            CPA_WAIT(0);
        }
        __syncthreads();

        const float* sA = smem + (buf ? OFF_A1 : OFF_A0);
        const float* sW = smem + (buf ? OFF_W1 : OFF_W0);

#pragma unroll
        for (int k8 = 0; k8 < 4; k8++) {
            const int kq = k8 * 8 + (lane & 3);
            const int rb = wm + (lane >> 2);
            const int nb = wn + (lane >> 2);
            uint32_t a[2][4], b[4][2];
#pragma unroll
            for (int tm = 0; tm < 2; tm++) {
                a[tm][0] = RNA13(__float_as_uint(sA[(rb + tm * 16 + 0) * 36 + kq]));
                a[tm][1] = RNA13(__float_as_uint(sA[(rb + tm * 16 + 8) * 36 + kq]));
                a[tm][2] = RNA13(__float_as_uint(sA[(rb + tm * 16 + 0) * 36 + kq + 4]));
                a[tm][3] = RNA13(__float_as_uint(sA[(rb + tm * 16 + 8) * 36 + kq + 4]));
            }
#pragma unroll
            for (int tn = 0; tn < 4; tn++) {
                float2 bp = *(const float2*)&sW[(nb + tn * 8) * 40 +
                                                k8 * 8 + 2 * (lane & 3)];
                b[tn][0] = __float_as_uint(bp.x);
                b[tn][1] = __float_as_uint(bp.y);
            }
#pragma unroll
            for (int tm = 0; tm < 2; tm++)
#pragma unroll
                for (int tn = 0; tn < 4; tn++)
                    MMA_TF32(acc[tm][tn], a[tm], b[tn]);
        }
        __syncthreads();
    }

    // ---- fused epilogue: fp16 store + attn logits (one head per warp) ----
    const float* satt_s = smem + OFF_ATTS;
    const float* satt_d = smem + OFF_ATTD;
    const int head = wn >> 5;
#pragma unroll
    for (int tm = 0; tm < 2; tm++)
#pragma unroll
        for (int h2 = 0; h2 < 2; h2++) {
            int gr = r0 + wm + tm * 16 + (lane >> 2) + 8 * h2;
            if (gr < M) {
#pragma unroll
                for (int tn = 0; tn < 4; tn++) {
                    __half2 hh = __floats2half2_rn(acc[tm][tn][2 * h2],
                                                   acc[tm][tn][2 * h2 + 1]);
                    *(uint32_t*)(h16 + (size_t)gr * 128 + wn + tn * 8 +
                                 (lane & 3) * 2) = *(uint32_t*)&hh;
                }
            }
            float s0 = 0.f, d0 = 0.f;
#pragma unroll
            for (int tn = 0; tn < 4; tn++) {
                int col = wn + tn * 8 + (lane & 3) * 2;
                float x0 = acc[tm][tn][2 * h2], x1 = acc[tm][tn][2 * h2 + 1];
                s0 += x0 * satt_s[col] + x1 * satt_s[col + 1];
                d0 += x0 * satt_d[col] + x1 * satt_d[col + 1];
            }
#pragma unroll
            for (int off = 1; off <= 2; off <<= 1) {
                s0 += __shfl_xor_sync(0xFFFFFFFF, s0, off);
                d0 += __shfl_xor_sync(0xFFFFFFFF, d0, off);
            }
            if ((lane & 3) == 0 && gr < M) {
                a_s[(size_t)gr * 4 + head] = s0;
                a_d[(size_t)gr * 4 + head] = d0;
            }
        }
}

// ---------------------------------------------------------------------------
// Classifier GEMM (exact fp32 FFMA2): C[M,40] = A @ Wpad[128,64] + b_out
// ---------------------------------------------------------------------------
__global__ void __launch_bounds__(256) gemm_cls_k(
    const float* __restrict__ A, const float* __restrict__ W,
    float* __restrict__ C, const float* __restrict__ bias_out, int M)
{
    __shared__ float sAT[32][130];
    __shared__ float sW[32][64];

    const int tid = threadIdx.x;
    const int tx = tid & 15;
    const int ty = tid >> 4;
    const int r0 = blockIdx.x * 128;

    ull acc[4][4];
#pragma unroll
    for (int p = 0; p < 4; p++)
#pragma unroll
        for (int c = 0; c < 4; c++) acc[p][c] = 0ull;

    for (int k0 = 0; k0 < 128; k0 += 32) {
#pragma unroll
        for (int i = 0; i < 4; i++) {
            int f = tid + i * 256;
            int row = f >> 3;
            int cg = f & 7;
            int grow = r0 + row;
            float4 v = make_float4(0.f, 0.f, 0.f, 0.f);
            if (grow < M)
                v = *(const float4*)(A + (size_t)grow * 128 + k0 + cg * 4);
            sAT[cg * 4 + 0][row] = v.x;
            sAT[cg * 4 + 1][row] = v.y;
            sAT[cg * 4 + 2][row] = v.z;
            sAT[cg * 4 + 3][row] = v.w;
        }
#pragma unroll
        for (int i = 0; i < 2; i++) {
            int f = tid + i * 256;
            int row = f >> 4;
            int cg = f & 15;
            *(float4*)&sW[row][cg * 4] =
                *(const float4*)(W + (size_t)(k0 + row) * 64 + cg * 4);
        }
        __syncthreads();

#pragma unroll 8
        for (int k = 0; k < 32; k++) {
            float4 w = *(float4*)&sW[k][tx * 4];
            ull b0, b1, b2, b3;
            PACK2(b0, w.x, w.x);
            PACK2(b1, w.y, w.y);
            PACK2(b2, w.z, w.z);
            PACK2(b3, w.w, w.w);
            const ull* ap = (const ull*)&sAT[k][ty * 8];
            ull a0 = ap[0], a1 = ap[1], a2 = ap[2], a3 = ap[3];
            FMA2(acc[0][0], a0, b0, acc[0][0]);
            FMA2(acc[0][1], a0, b1, acc[0][1]);
            FMA2(acc[0][2], a0, b2, acc[0][2]);
            FMA2(acc[0][3], a0, b3, acc[0][3]);
            FMA2(acc[1][0], a1, b0, acc[1][0]);
            FMA2(acc[1][1], a1, b1, acc[1][1]);
            FMA2(acc[1][2], a1, b2, acc[1][2]);
            FMA2(acc[1][3], a1, b3, acc[1][3]);
            FMA2(acc[2][0], a2, b0, acc[2][0]);
            FMA2(acc[2][1], a2, b1, acc[2][1]);
            FMA2(acc[2][2], a2, b2, acc[2][2]);
            FMA2(acc[2][3], a2, b3, acc[2][3]);
            FMA2(acc[3][0], a3, b0, acc[3][0]);
            FMA2(acc[3][1], a3, b1, acc[3][1]);
            FMA2(acc[3][2], a3, b2, acc[3][2]);
            FMA2(acc[3][3], a3, b3, acc[3][3]);
        }
        __syncthreads();
    }

    int col = tx * 4;
    if (col < 40) {
        float4 bo = *(const float4*)(bias_out + col);
#pragma unroll
        for (int p = 0; p < 4; p++) {
            float4 v0, v1;
            UNPK2(v0.x, v1.x, acc[p][0]);
            UNPK2(v0.y, v1.y, acc[p][1]);
            UNPK2(v0.z, v1.z, acc[p][2]);
            UNPK2(v0.w, v1.w, acc[p][3]);
            int gr0 = r0 + ty * 8 + 2 * p;
            if (gr0 < M) {
                v0.x += bo.x; v0.y += bo.y; v0.z += bo.z; v0.w += bo.w;
                *(float4*)(C + (size_t)gr0 * 40 + col) = v0;
            }
            if (gr0 + 1 < M) {
                v1.x += bo.x; v1.y += bo.y; v1.z += bo.z; v1.w += bo.w;
                *(float4*)(C + (size_t)(gr0 + 1) * 40 + col) = v1;
            }
        }
    }
}

// ---------------------------------------------------------------------------
// prep: pad Wc, build W1^T/W2^T tf32-rounded k-pair-interleaved, seed counts
// ---------------------------------------------------------------------------
__global__ void prep_k(const float* __restrict__ wc, float* __restrict__ wpad,
                       const float* __restrict__ w1, float* __restrict__ w1tf,
                       const float* __restrict__ w2, float* __restrict__ w2tf,
                       int* __restrict__ cnt, int N)
{
    int t = blockIdx.x * blockDim.x + threadIdx.x;
    if (t < 128 * 64) {
        int r = t >> 6, c = t & 63;
        wpad[t] = (c < 40) ? wc[r * 40 + c] : 0.f;
    }
    if (t < 128 * 128) {
        int n = t >> 7, j = t & 127;
        int k = ((j >> 3) << 3) + ((j >> 1) & 3) + ((j & 1) << 2);
        w1tf[t] = __uint_as_float(f2tf(w1[k * 128 + n]));
        w2tf[t] = __uint_as_float(f2tf(w2[k * 128 + n]));
    }
    if (t < N) cnt[t] = 1;
}

// ---------------------------------------------------------------------------
// CSR build: count, 3-kernel scan, scatter fill
// ---------------------------------------------------------------------------
__global__ void count_k(const int* __restrict__ ei, int E, int* __restrict__ cnt)
{
    int i = blockIdx.x * blockDim.x + threadIdx.x;
    if (i < E) atomicAdd(cnt + __ldg(ei + E + i), 1);
}

__global__ void blocksum_k(const int* __restrict__ cnt, int* __restrict__ bsum, int N)
{
    __shared__ int s[256];
    int i = blockIdx.x * 256 + threadIdx.x;
    s[threadIdx.x] = (i < N) ? cnt[i] : 0;
    __syncthreads();
#pragma unroll
    for (int st = 128; st > 0; st >>= 1) {
        if (threadIdx.x < st) s[threadIdx.x] += s[threadIdx.x + st];
        __syncthreads();
    }
    if (threadIdx.x == 0) bsum[blockIdx.x] = s[0];
}

__global__ void scan_bsums_k(int* __restrict__ bsum, int NB)
{
    __shared__ int s[NBMAX];
    int t = threadIdx.x;
    int x = (t < NB) ? bsum[t] : 0;
    s[t] = x;
    __syncthreads();
#pragma unroll
    for (int off = 1; off < NBMAX; off <<= 1) {
        int v = (t >= off) ? s[t - off] : 0;
        __syncthreads();
        s[t] += v;
        __syncthreads();
    }
    bsum[t < NBMAX ? t : 0] = s[t] - x;
}

__global__ void scan_final_k(const int* __restrict__ cnt,
                             const int* __restrict__ boff,
                             int* __restrict__ rowptr,
                             int* __restrict__ wcur, int N)
{
    __shared__ int s[256];
    int t = threadIdx.x;
    int i = blockIdx.x * 256 + t;
    int x = (i < N) ? cnt[i] : 0;
    s[t] = x;
    __syncthreads();
#pragma unroll
    for (int off = 1; off < 256; off <<= 1) {
        int v = (t >= off) ? s[t - off] : 0;
        __syncthreads();
        s[t] += v;
        __syncthreads();
    }
    int excl = s[t] - x + boff[blockIdx.x];
    if (i < N) {
        rowptr[i] = excl;
        wcur[i] = excl;
        if (i == N - 1) rowptr[N] = excl + x;
    }
}

__global__ void fill_k(const int* __restrict__ ei, int E, int N,
                       int* __restrict__ wcur, int* __restrict__ csrc)
{
    int t = blockIdx.x * blockDim.x + threadIdx.x;
    int T = E + N;
    if (t >= T) return;
    int s, d;
    if (t < E) { s = __ldg(ei + t); d = __ldg(ei + E + t); }
    else       { s = t - E; d = s; }
    int pos = atomicAdd(wcur + d, 1);
    csrc[pos] = s;
}

// ---------------------------------------------------------------------------
// Aggregation: warp per dst node; two half-warps, 1-deep prefetch each.
// Epilogue applies relu(x*inv + bias). Works on a node-range via offset ptrs.
// ---------------------------------------------------------------------------
__global__ void __launch_bounds__(256) agg_k(
    const int* __restrict__ rowptr, const int* __restrict__ csrc,
    const __half* __restrict__ h16,
    const float* __restrict__ a_s, const float* __restrict__ a_d,
    const float* __restrict__ bias, float* __restrict__ out, int N)
{
    int d = (blockIdx.x * blockDim.x + threadIdx.x) >> 5;
    int lane = threadIdx.x & 31;
    if (d >= N) return;

    const int half = lane >> 4;
    const int sl = lane & 15;
    const int head = sl >> 2;
    int beg = __ldg(rowptr + d);
    int end = __ldg(rowptr + d + 1);
    float ed = __ldg(a_d + 4 * (size_t)d + head);

    float acc[8];
#pragma unroll
    for (int j = 0; j < 8; j++) acc[j] = 0.f;
    float den = 0.f;

    int e = beg + half;
    if (e < end) {
        int s = __ldg(csrc + e);
        float es = __ldg(a_s + 4 * (size_t)s + head);
        uint4 pk = *(const uint4*)(h16 + (size_t)s * 128 + sl * 8);
        for (;;) {
            int e2 = e + 2;
            bool more = e2 < end;
            float esN = 0.f;
            uint4 pkN = make_uint4(0, 0, 0, 0);
            if (more) {
                int sn = __ldg(csrc + e2);
                esN = __ldg(a_s + 4 * (size_t)sn + head);
                pkN = *(const uint4*)(h16 + (size_t)sn * 128 + sl * 8);
            }
            float t = es + ed;
            t = (t > 0.f) ? t : 0.2f * t;
            float p = __expf(t);
            den += p;
            const __half2* hp = (const __half2*)&pk;
#pragma unroll
            for (int j = 0; j < 4; j++) {
                float2 f = __half22float2(hp[j]);
                acc[2 * j] = fmaf(p, f.x, acc[2 * j]);
                acc[2 * j + 1] = fmaf(p, f.y, acc[2 * j + 1]);
            }
            if (!more) break;
            e = e2; es = esN; pk = pkN;
        }
    }

#pragma unroll
    for (int j = 0; j < 8; j++)
        acc[j] += __shfl_down_sync(0xFFFFFFFF, acc[j], 16);
    den += __shfl_down_sync(0xFFFFFFFF, den, 16);

    if (half == 0) {
        float inv = 1.0f / (den + 1e-16f);
        float4 b0 = *(const float4*)(bias + sl * 8);
        float4 b1 = *(const float4*)(bias + sl * 8 + 4);
        float4 v0 = make_float4(fmaxf(fmaf(acc[0], inv, b0.x), 0.f),
                                fmaxf(fmaf(acc[1], inv, b0.y), 0.f),
                                fmaxf(fmaf(acc[2], inv, b0.z), 0.f),
                                fmaxf(fmaf(acc[3], inv, b0.w), 0.f));
        float4 v1 = make_float4(fmaxf(fmaf(acc[4], inv, b1.x), 0.f),
                                fmaxf(fmaf(acc[5], inv, b1.y), 0.f),
                                fmaxf(fmaf(acc[6], inv, b1.z), 0.f),
                                fmaxf(fmaf(acc[7], inv, b1.w), 0.f));
        float4* o = (float4*)(out + (size_t)d * 128 + sl * 8);
        o[0] = v0;
        o[1] = v1;
    }
}

// ---------------------------------------------------------------------------
extern "C" void kernel_launch(void* const* d_in, const int* in_sizes, int n_in,
                              void* d_out, int out_size)
{
    const float* x   = (const float*)d_in[0];
    const int*   ei  = (const int*)  d_in[1];
    const float* W1  = (const float*)d_in[2];
    const float* as1 = (const float*)d_in[3];
    const float* ad1 = (const float*)d_in[4];
    const float* b1  = (const float*)d_in[5];
    const float* W2  = (const float*)d_in[6];
    const float* as2 = (const float*)d_in[7];
    const float* ad2 = (const float*)d_in[8];
    const float* b2  = (const float*)d_in[9];
    const float* Wc  = (const float*)d_in[10];
    const float* bc  = (const float*)d_in[11];
    float* out = (float*)d_out;

    const int N = in_sizes[0] / 128;
    const int E = in_sizes[1] / 2;

    __half *h16a, *h16b;
    float *obuf, *asbA, *adbA, *asbB, *adbB, *wpad, *w1tf, *w2tf;
    int *rowptr, *wcur, *csrc, *bsum;
    cudaGetSymbolAddress((void**)&h16a,   g_h16a);
    cudaGetSymbolAddress((void**)&h16b,   g_h16b);
    cudaGetSymbolAddress((void**)&obuf,   g_out);
    cudaGetSymbolAddress((void**)&asbA,   g_asrcA);
    cudaGetSymbolAddress((void**)&adbA,   g_adstA);
    cudaGetSymbolAddress((void**)&asbB,   g_asrcB);
    cudaGetSymbolAddress((void**)&adbB,   g_adstB);
    cudaGetSymbolAddress((void**)&wpad,   g_wpad);
    cudaGetSymbolAddress((void**)&w1tf,   g_w1tf);
    cudaGetSymbolAddress((void**)&w2tf,   g_w2tf);
    cudaGetSymbolAddress((void**)&rowptr, g_rowptr);
    cudaGetSymbolAddress((void**)&wcur,   g_wcur);
    cudaGetSymbolAddress((void**)&csrc,   g_csrc);
    cudaGetSymbolAddress((void**)&bsum,   g_bsum);

    // one-time host-side init (no device allocations)
    static cudaStream_t s2 = nullptr;
    static cudaEvent_t evF, evCSR, evA2, evA3;
    if (!s2) {
        cudaStreamCreateWithFlags(&s2, cudaStreamNonBlocking);
        cudaEventCreateWithFlags(&evF,   cudaEventDisableTiming);
        cudaEventCreateWithFlags(&evCSR, cudaEventDisableTiming);
        cudaEventCreateWithFlags(&evA2,  cudaEventDisableTiming);
        cudaEventCreateWithFlags(&evA3,  cudaEventDisableTiming);
        cudaFuncSetAttribute(mma_gemm_k,
                             cudaFuncAttributeMaxDynamicSharedMemorySize,
                             SMEM_FLOATS * 4);
    }

    // phase-2 chunk split (tile-aligned -> bit-identical results)
    const int NH0 = ((N / 2 + 127) / 128) * 128;   // 50048 for N=100000
    const int NH1 = N - NH0;

    const dim3 gMma((N + 127) / 128);
    const dim3 gClsH0((NH0 + 127) / 128), gClsH1((NH1 + 127) / 128);
    const int  NB = (N + 255) / 256;
    const int  T = E + N;
    const int  gAgg = (N + 7) / 8;
    const int  gAggH0 = (NH0 + 7) / 8, gAggH1 = (NH1 + 7) / 8;
    const int  smb = SMEM_FLOATS * 4;

    // ---- phase 0: prep (main), fork CSR chain to s2, GEMM1 on main ----
    prep_k<<<NB, 256>>>(Wc, wpad, W1, w1tf, W2, w2tf, wcur, N);
    cudaEventRecord(evF, 0);
    cudaStreamWaitEvent(s2, evF, 0);

    count_k<<<(E + 255) / 256, 256, 0, s2>>>(ei, E, wcur);
    blocksum_k<<<NB, 256, 0, s2>>>(wcur, bsum, N);
    mma_gemm_k<<<gMma, 512, smb>>>(x, w1tf, h16a, asbA, adbA, as1, ad1, N);
    scan_bsums_k<<<1, NBMAX, 0, s2>>>(bsum, NB);
    scan_final_k<<<NB, 256, 0, s2>>>(wcur, bsum, rowptr, wcur, N);
    fill_k<<<(T + 255) / 256, 256, 0, s2>>>(ei, E, N, wcur, csrc);
    cudaEventRecord(evCSR, s2);
    cudaStreamWaitEvent(0, evCSR, 0);

    // ---- phase 1 (serial, as in R12): full agg1, full GEMM2 ----
    agg_k<<<gAgg, 256>>>(rowptr, csrc, h16a, asbA, adbA, b1, obuf, N);
    mma_gemm_k<<<gMma, 512, smb>>>(obuf, w2tf, h16b, asbB, adbB, as2, ad2, N);

    // ---- phase 2: agg2 staggered with classifier (complementary pipes) ----
    agg_k<<<gAggH0, 256>>>(rowptr, csrc, h16b, asbB, adbB, b2, obuf, NH0);
    cudaEventRecord(evA2, 0);
    cudaStreamWaitEvent(s2, evA2, 0);
    // s2: agg2 chunk 1 (writes obuf[NH0:]) concurrent with cls chunk 0
    agg_k<<<gAggH1, 256, 0, s2>>>(rowptr + NH0, csrc, h16b, asbB,
                                  adbB + 4 * (size_t)NH0, b2,
                                  obuf + (size_t)NH0 * 128, NH1);
    cudaEventRecord(evA3, s2);
    // main: cls chunk 0 (reads obuf[0:NH0) — disjoint from agg2 chunk 1)
    gemm_cls_k<<<gClsH0, 256>>>(obuf, wpad, out, bc, NH0);
    cudaStreamWaitEvent(0, evA3, 0);
    gemm_cls_k<<<gClsH1, 256>>>(obuf + (size_t)NH0 * 128, wpad,
                                out + (size_t)NH0 * 40, bc, NH1);
}

// round 16
// speedup vs baseline: 1.0187x; 1.0030x over previous
#include <cuda_runtime.h>
#include <cuda_fp16.h>
#include <cstdint>

#define NN 100000
#define FDIM 128
#define EMAX 1700032
#define NBMAX 512

typedef unsigned long long ull;

// Scratch (device globals — allocation-free per harness rules)
__device__ __half g_h16[NN * FDIM];   // fp16 transformed features (messages)
__device__ float g_out[NN * FDIM];    // aggregated + relu(·+bias) output (fp32)
__device__ float g_asrc[NN * 4];
__device__ float g_adst[NN * 4];
__device__ float g_wpad[FDIM * 64];   // Wc zero-padded to 128x64
__device__ float g_w1tf[FDIM * FDIM]; // W1^T, tf32-rounded (natural k order)
__device__ float g_w2tf[FDIM * FDIM]; // W2^T, tf32-rounded (natural k order)
__device__ int   g_rowptr[NN + 1];
__device__ int   g_wcur[NN];
__device__ int   g_csrc[EMAX];
__device__ int   g_bsum[NBMAX];

// ---------------------------------------------------------------------------
// packed f32x2 helpers (classifier GEMM)
// ---------------------------------------------------------------------------
#define PACK2(out, lo, hi) \
    asm("mov.b64 %0, {%1, %2};" : "=l"(out) : "f"(lo), "f"(hi))
#define UNPK2(lo, hi, in) \
    asm("mov.b64 {%0, %1}, %2;" : "=f"(lo), "=f"(hi) : "l"(in))
#define FMA2(d, a, b, c) \
    asm("fma.rn.f32x2 %0, %1, %2, %3;" : "=l"(d) : "l"(a), "l"(b), "l"(c))

__device__ __forceinline__ uint32_t f2tf(float f) {
    uint32_t r;
    asm("cvt.rna.tf32.f32 %0, %1;" : "=r"(r) : "f"(f));
    return r;
}
#define MMA_TF32(c, a, b) \
    asm volatile("mma.sync.aligned.m16n8k8.row.col.f32.tf32.tf32.f32 " \
        "{%0,%1,%2,%3}, {%4,%5,%6,%7}, {%8,%9}, {%0,%1,%2,%3};" \
        : "+f"((c)[0]), "+f"((c)[1]), "+f"((c)[2]), "+f"((c)[3]) \
        : "r"((a)[0]), "r"((a)[1]), "r"((a)[2]), "r"((a)[3]), \
          "r"((b)[0]), "r"((b)[1]))

__device__ __forceinline__ uint32_t s2u(const void* p) {
    uint32_t a;
    asm("{ .reg .u64 t; cvta.to.shared.u64 t, %1; cvt.u32.u64 %0, t; }"
        : "=r"(a) : "l"(p));
    return a;
}
__device__ __forceinline__ void cpa16(uint32_t dst, const void* src, bool pred) {
    int sz = pred ? 16 : 0;   // src-size 0 -> zero-fill, no read
    asm volatile("cp.async.ca.shared.global [%0], [%1], 16, %2;"
                 :: "r"(dst), "l"(src), "r"(sz));
}
#define CPA_COMMIT() asm volatile("cp.async.commit_group;" ::: "memory")
#define CPA_WAIT(n)  asm volatile("cp.async.wait_group %0;" :: "n"(n) : "memory")

// rna-to-tf32 via bit trick: fp32 is sign-magnitude, so adding 0x1000 and
// letting the tensor core truncate the low 13 bits == cvt.rna.tf32.f32.
#define RNA13(u) ((u) + 0x1000u)

// dynamic smem layout (floats): A/W double-buffered, BOTH stride 40
// (8B-access conflict-free: 20*r + q distinct mod 16)
#define OFF_A0   0
#define OFF_A1   5120        // 128*40
#define OFF_W0   10240
#define OFF_W1   15360
#define OFF_ATTS 20480
#define OFF_ATTD 20608
#define SMEM_FLOATS 20736    // 82944 bytes

// ---------------------------------------------------------------------------
// TF32 tensor GEMM, cp.async double-buffered, fused attention epilogue.
// 512 threads, 16 warps (4M x 4N), warp tile 32x32.
// k-relabeling: mma-k q <-> source-k 2q, mma-k q+4 <-> source-k 2q+1.
// => BOTH A and B fragment pairs are adjacent in natural row-major order:
//    per k8 step, 8 x LDS.64 total (was 8 x LDS.32 + 4 x LDS.64).
// ---------------------------------------------------------------------------
__global__ void __launch_bounds__(512) mma_gemm_k(
    const float* __restrict__ A, const float* __restrict__ WtfT,
    __half* __restrict__ h16,
    float* __restrict__ a_s, float* __restrict__ a_d,
    const float* __restrict__ att_s, const float* __restrict__ att_d, int M)
{
    extern __shared__ float smem[];
    const uint32_t sb = s2u(smem);
    const int tid = threadIdx.x;
    const int lane = tid & 31;
    const int w = tid >> 5;
    const int wm = (w & 3) * 32;
    const int wn = (w >> 2) * 32;      // one head per warp
    const int r0 = blockIdx.x * 128;

    if (tid < 128) {
        smem[OFF_ATTS + tid] = att_s[tid];
        smem[OFF_ATTD + tid] = att_d[tid];
    }

    auto load_slab = [&](int kb, int buf) {
        const uint32_t aB = sb + (buf ? OFF_A1 : OFF_A0) * 4;
        const uint32_t wB = sb + (buf ? OFF_W1 : OFF_W0) * 4;
        // A: 128 rows x 8 float4 = 1024; 2 per thread (natural order)
#pragma unroll
        for (int i = 0; i < 2; i++) {
            int idx = tid + i * 512;
            int row = idx >> 3, cg = idx & 7;
            int g = r0 + row;
            bool ok = g < M;
            cpa16(aB + (row * 40 + cg * 4) * 4,
                  A + (size_t)(ok ? g : 0) * 128 + kb * 32 + cg * 4, ok);
        }
        // W^T: 128 n-rows x 8 float4 (natural k order); 2 per thread
#pragma unroll
        for (int i = 0; i < 2; i++) {
            int idx = tid + i * 512;
            int n = idx >> 3, cg = idx & 7;
            cpa16(wB + (n * 40 + cg * 4) * 4,
                  WtfT + (size_t)n * 128 + kb * 32 + cg * 4, true);
        }
    };

    float acc[2][4][4];
#pragma unroll
    for (int tm = 0; tm < 2; tm++)
#pragma unroll
        for (int tn = 0; tn < 4; tn++)
#pragma unroll
            for (int i = 0; i < 4; i++) acc[tm][tn][i] = 0.f;

    load_slab(0, 0);
    CPA_COMMIT();

#pragma unroll
    for (int kb = 0; kb < 4; kb++) {
        const int buf = kb & 1;
        if (kb < 3) {
            load_slab(kb + 1, buf ^ 1);
            CPA_COMMIT();
            CPA_WAIT(1);
        } else {
            CPA_WAIT(0);
        }
        __syncthreads();

        const float* sA = smem + (buf ? OFF_A1 : OFF_A0);
        const float* sW = smem + (buf ? OFF_W1 : OFF_W0);

#pragma unroll
        for (int k8 = 0; k8 < 4; k8++) {
            const int kp = k8 * 8 + 2 * (lane & 3);   // source-k pair base
            const int rb = wm + (lane >> 2);
            const int nb = wn + (lane >> 2);
            uint32_t a[2][4], b[4][2];
#pragma unroll
            for (int tm = 0; tm < 2; tm++) {
                float2 p0 = *(const float2*)&sA[(rb + tm * 16 + 0) * 40 + kp];
                float2 p1 = *(const float2*)&sA[(rb + tm * 16 + 8) * 40 + kp];
                a[tm][0] = RNA13(__float_as_uint(p0.x));  // mma-k q
                a[tm][2] = RNA13(__float_as_uint(p0.y));  // mma-k q+4
                a[tm][1] = RNA13(__float_as_uint(p1.x));
                a[tm][3] = RNA13(__float_as_uint(p1.y));
            }
#pragma unroll
            for (int tn = 0; tn < 4; tn++) {
                float2 bp = *(const float2*)&sW[(nb + tn * 8) * 40 + kp];
                b[tn][0] = __float_as_uint(bp.x);
                b[tn][1] = __float_as_uint(bp.y);
            }
#pragma unroll
            for (int tm = 0; tm < 2; tm++)
#pragma unroll
                for (int tn = 0; tn < 4; tn++)
                    MMA_TF32(acc[tm][tn], a[tm], b[tn]);
        }
        __syncthreads();
    }

    // ---- fused epilogue: fp16 store + attn logits (one head per warp) ----
    const float* satt_s = smem + OFF_ATTS;
    const float* satt_d = smem + OFF_ATTD;
    const int head = wn >> 5;
#pragma unroll
    for (int tm = 0; tm < 2; tm++)
#pragma unroll
        for (int h2 = 0; h2 < 2; h2++) {
            int gr = r0 + wm + tm * 16 + (lane >> 2) + 8 * h2;
            if (gr < M) {
#pragma unroll
                for (int tn = 0; tn < 4; tn++) {
                    __half2 hh = __floats2half2_rn(acc[tm][tn][2 * h2],
                                                   acc[tm][tn][2 * h2 + 1]);
                    *(uint32_t*)(h16 + (size_t)gr * 128 + wn + tn * 8 +
                                 (lane & 3) * 2) = *(uint32_t*)&hh;
                }
            }
            float s0 = 0.f, d0 = 0.f;
#pragma unroll
            for (int tn = 0; tn < 4; tn++) {
                int col = wn + tn * 8 + (lane & 3) * 2;
                float x0 = acc[tm][tn][2 * h2], x1 = acc[tm][tn][2 * h2 + 1];
                s0 += x0 * satt_s[col] + x1 * satt_s[col + 1];
                d0 += x0 * satt_d[col] + x1 * satt_d[col + 1];
            }
#pragma unroll
            for (int off = 1; off <= 2; off <<= 1) {
                s0 += __shfl_xor_sync(0xFFFFFFFF, s0, off);
                d0 += __shfl_xor_sync(0xFFFFFFFF, d0, off);
            }
            if ((lane & 3) == 0 && gr < M) {
                a_s[(size_t)gr * 4 + head] = s0;
                a_d[(size_t)gr * 4 + head] = d0;
            }
        }
}

// ---------------------------------------------------------------------------
// Classifier GEMM (exact fp32 FFMA2): C[M,40] = A @ Wpad[128,64] + b_out
// ---------------------------------------------------------------------------
__global__ void __launch_bounds__(256) gemm_cls_k(
    const float* __restrict__ A, const float* __restrict__ W,
    float* __restrict__ C, const float* __restrict__ bias_out, int M)
{
    __shared__ float sAT[32][130];
    __shared__ float sW[32][64];

    const int tid = threadIdx.x;
    const int tx = tid & 15;
    const int ty = tid >> 4;
    const int r0 = blockIdx.x * 128;

    ull acc[4][4];
#pragma unroll
    for (int p = 0; p < 4; p++)
#pragma unroll
        for (int c = 0; c < 4; c++) acc[p][c] = 0ull;

    for (int k0 = 0; k0 < 128; k0 += 32) {
#pragma unroll
        for (int i = 0; i < 4; i++) {
            int f = tid + i * 256;
            int row = f >> 3;
            int cg = f & 7;
            int grow = r0 + row;
            float4 v = make_float4(0.f, 0.f, 0.f, 0.f);
            if (grow < M)
                v = *(const float4*)(A + (size_t)grow * 128 + k0 + cg * 4);
            sAT[cg * 4 + 0][row] = v.x;
            sAT[cg * 4 + 1][row] = v.y;
            sAT[cg * 4 + 2][row] = v.z;
            sAT[cg * 4 + 3][row] = v.w;
        }
#pragma unroll
        for (int i = 0; i < 2; i++) {
            int f = tid + i * 256;
            int row = f >> 4;
            int cg = f & 15;
            *(float4*)&sW[row][cg * 4] =
                *(const float4*)(W + (size_t)(k0 + row) * 64 + cg * 4);
        }
        __syncthreads();

#pragma unroll 8
        for (int k = 0; k < 32; k++) {
            float4 w = *(float4*)&sW[k][tx * 4];
            ull b0, b1, b2, b3;
            PACK2(b0, w.x, w.x);
            PACK2(b1, w.y, w.y);
            PACK2(b2, w.z, w.z);
            PACK2(b3, w.w, w.w);
            const ull* ap = (const ull*)&sAT[k][ty * 8];
            ull a0 = ap[0], a1 = ap[1], a2 = ap[2], a3 = ap[3];
            FMA2(acc[0][0], a0, b0, acc[0][0]);
            FMA2(acc[0][1], a0, b1, acc[0][1]);
            FMA2(acc[0][2], a0, b2, acc[0][2]);
            FMA2(acc[0][3], a0, b3, acc[0][3]);
            FMA2(acc[1][0], a1, b0, acc[1][0]);
            FMA2(acc[1][1], a1, b1, acc[1][1]);
            FMA2(acc[1][2], a1, b2, acc[1][2]);
            FMA2(acc[1][3], a1, b3, acc[1][3]);
            FMA2(acc[2][0], a2, b0, acc[2][0]);
            FMA2(acc[2][1], a2, b1, acc[2][1]);
            FMA2(acc[2][2], a2, b2, acc[2][2]);
            FMA2(acc[2][3], a2, b3, acc[2][3]);
            FMA2(acc[3][0], a3, b0, acc[3][0]);
            FMA2(acc[3][1], a3, b1, acc[3][1]);
            FMA2(acc[3][2], a3, b2, acc[3][2]);
            FMA2(acc[3][3], a3, b3, acc[3][3]);
        }
        __syncthreads();
    }

    int col = tx * 4;
    if (col < 40) {
        float4 bo = *(const float4*)(bias_out + col);
#pragma unroll
        for (int p = 0; p < 4; p++) {
            float4 v0, v1;
            UNPK2(v0.x, v1.x, acc[p][0]);
            UNPK2(v0.y, v1.y, acc[p][1]);
            UNPK2(v0.z, v1.z, acc[p][2]);
            UNPK2(v0.w, v1.w, acc[p][3]);
            int gr0 = r0 + ty * 8 + 2 * p;
            if (gr0 < M) {
                v0.x += bo.x; v0.y += bo.y; v0.z += bo.z; v0.w += bo.w;
                *(float4*)(C + (size_t)gr0 * 40 + col) = v0;
            }
            if (gr0 + 1 < M) {
                v1.x += bo.x; v1.y += bo.y; v1.z += bo.z; v1.w += bo.w;
                *(float4*)(C + (size_t)(gr0 + 1) * 40 + col) = v1;
            }
        }
    }
}

// ---------------------------------------------------------------------------
// prep: pad Wc, build W1^T/W2^T tf32-rounded (natural k order), seed counts
// ---------------------------------------------------------------------------
__global__ void prep_k(const float* __restrict__ wc, float* __restrict__ wpad,
                       const float* __restrict__ w1, float* __restrict__ w1tf,
                       const float* __restrict__ w2, float* __restrict__ w2tf,
                       int* __restrict__ cnt, int N)
{
    int t = blockIdx.x * blockDim.x + threadIdx.x;
    if (t < 128 * 64) {
        int r = t >> 6, c = t & 63;
        wpad[t] = (c < 40) ? wc[r * 40 + c] : 0.f;
    }
    if (t < 128 * 128) {
        int n = t >> 7, k = t & 127;
        w1tf[t] = __uint_as_float(f2tf(w1[k * 128 + n]));
        w2tf[t] = __uint_as_float(f2tf(w2[k * 128 + n]));
    }
    if (t < N) cnt[t] = 1;
}

// ---------------------------------------------------------------------------
// CSR build: count, 3-kernel scan, scatter fill
// ---------------------------------------------------------------------------
__global__ void count_k(const int* __restrict__ ei, int E, int* __restrict__ cnt)
{
    int i = blockIdx.x * blockDim.x + threadIdx.x;
    if (i < E) atomicAdd(cnt + __ldg(ei + E + i), 1);
}

__global__ void blocksum_k(const int* __restrict__ cnt, int* __restrict__ bsum, int N)
{
    __shared__ int s[256];
    int i = blockIdx.x * 256 + threadIdx.x;
    s[threadIdx.x] = (i < N) ? cnt[i] : 0;
    __syncthreads();
#pragma unroll
    for (int st = 128; st > 0; st >>= 1) {
        if (threadIdx.x < st) s[threadIdx.x] += s[threadIdx.x + st];
        __syncthreads();
    }
    if (threadIdx.x == 0) bsum[blockIdx.x] = s[0];
}

__global__ void scan_bsums_k(int* __restrict__ bsum, int NB)
{
    __shared__ int s[NBMAX];
    int t = threadIdx.x;
    int x = (t < NB) ? bsum[t] : 0;
    s[t] = x;
    __syncthreads();
#pragma unroll
    for (int off = 1; off < NBMAX; off <<= 1) {
        int v = (t >= off) ? s[t - off] : 0;
        __syncthreads();
        s[t] += v;
        __syncthreads();
    }
    bsum[t < NBMAX ? t : 0] = s[t] - x;
}

__global__ void scan_final_k(const int* __restrict__ cnt,
                             const int* __restrict__ boff,
                             int* __restrict__ rowptr,
                             int* __restrict__ wcur, int N)
{
    __shared__ int s[256];
    int t = threadIdx.x;
    int i = blockIdx.x * 256 + t;
    int x = (i < N) ? cnt[i] : 0;
    s[t] = x;
    __syncthreads();
#pragma unroll
    for (int off = 1; off < 256; off <<= 1) {
        int v = (t >= off) ? s[t - off] : 0;
        __syncthreads();
        s[t] += v;
        __syncthreads();
    }
    int excl = s[t] - x + boff[blockIdx.x];
    if (i < N) {
        rowptr[i] = excl;
        wcur[i] = excl;
        if (i == N - 1) rowptr[N] = excl + x;
    }
}

__global__ void fill_k(const int* __restrict__ ei, int E, int N,
                       int* __restrict__ wcur, int* __restrict__ csrc)
{
    int t = blockIdx.x * blockDim.x + threadIdx.x;
    int T = E + N;
    if (t >= T) return;
    int s, d;
    if (t < E) { s = __ldg(ei + t); d = __ldg(ei + E + t); }
    else       { s = t - E; d = s; }
    int pos = atomicAdd(wcur + d, 1);
    csrc[pos] = s;
}

// ---------------------------------------------------------------------------
// Aggregation: warp per dst node; two half-warps, 1-deep prefetch each.
// Epilogue applies relu(x*inv + bias).
// ---------------------------------------------------------------------------
__global__ void __launch_bounds__(256) agg_k(
    const int* __restrict__ rowptr, const int* __restrict__ csrc,
    const __half* __restrict__ h16,
    const float* __restrict__ a_s, const float* __restrict__ a_d,
    const float* __restrict__ bias, float* __restrict__ out, int N)
{
    int d = (blockIdx.x * blockDim.x + threadIdx.x) >> 5;
    int lane = threadIdx.x & 31;
    if (d >= N) return;

    const int half = lane >> 4;
    const int sl = lane & 15;
    const int head = sl >> 2;
    int beg = __ldg(rowptr + d);
    int end = __ldg(rowptr + d + 1);
    float ed = __ldg(a_d + 4 * (size_t)d + head);

    float acc[8];
#pragma unroll
    for (int j = 0; j < 8; j++) acc[j] = 0.f;
    float den = 0.f;

    int e = beg + half;
    if (e < end) {
        int s = __ldg(csrc + e);
        float es = __ldg(a_s + 4 * (size_t)s + head);
        uint4 pk = *(const uint4*)(h16 + (size_t)s * 128 + sl * 8);
        for (;;) {
            int e2 = e + 2;
            bool more = e2 < end;
            float esN = 0.f;
            uint4 pkN = make_uint4(0, 0, 0, 0);
            if (more) {
                int sn = __ldg(csrc + e2);
                esN = __ldg(a_s + 4 * (size_t)sn + head);
                pkN = *(const uint4*)(h16 + (size_t)sn * 128 + sl * 8);
            }
            float t = es + ed;
            t = (t > 0.f) ? t : 0.2f * t;
            float p = __expf(t);
            den += p;
            const __half2* hp = (const __half2*)&pk;
#pragma unroll
            for (int j = 0; j < 4; j++) {
                float2 f = __half22float2(hp[j]);
                acc[2 * j] = fmaf(p, f.x, acc[2 * j]);
                acc[2 * j + 1] = fmaf(p, f.y, acc[2 * j + 1]);
            }
            if (!more) break;
            e = e2; es = esN; pk = pkN;
        }
    }

#pragma unroll
    for (int j = 0; j < 8; j++)
        acc[j] += __shfl_down_sync(0xFFFFFFFF, acc[j], 16);
    den += __shfl_down_sync(0xFFFFFFFF, den, 16);

    if (half == 0) {
        float inv = 1.0f / (den + 1e-16f);
        float4 b0 = *(const float4*)(bias + sl * 8);
        float4 b1 = *(const float4*)(bias + sl * 8 + 4);
        float4 v0 = make_float4(fmaxf(fmaf(acc[0], inv, b0.x), 0.f),
                                fmaxf(fmaf(acc[1], inv, b0.y), 0.f),
                                fmaxf(fmaf(acc[2], inv, b0.z), 0.f),
                                fmaxf(fmaf(acc[3], inv, b0.w), 0.f));
        float4 v1 = make_float4(fmaxf(fmaf(acc[4], inv, b1.x), 0.f),
                                fmaxf(fmaf(acc[5], inv, b1.y), 0.f),
                                fmaxf(fmaf(acc[6], inv, b1.z), 0.f),
                                fmaxf(fmaf(acc[7], inv, b1.w), 0.f));
        float4* o = (float4*)(out + (size_t)d * 128 + sl * 8);
        o[0] = v0;
        o[1] = v1;
    }
}

// ---------------------------------------------------------------------------
extern "C" void kernel_launch(void* const* d_in, const int* in_sizes, int n_in,
                              void* d_out, int out_size)
{
    const float* x   = (const float*)d_in[0];
    const int*   ei  = (const int*)  d_in[1];
    const float* W1  = (const float*)d_in[2];
    const float* as1 = (const float*)d_in[3];
    const float* ad1 = (const float*)d_in[4];
    const float* b1  = (const float*)d_in[5];
    const float* W2  = (const float*)d_in[6];
    const float* as2 = (const float*)d_in[7];
    const float* ad2 = (const float*)d_in[8];
    const float* b2  = (const float*)d_in[9];
    const float* Wc  = (const float*)d_in[10];
    const float* bc  = (const float*)d_in[11];
    float* out = (float*)d_out;

    const int N = in_sizes[0] / 128;
    const int E = in_sizes[1] / 2;

    __half* h16;
    float *obuf, *asb, *adb, *wpad, *w1tf, *w2tf;
    int *rowptr, *wcur, *csrc, *bsum;
    cudaGetSymbolAddress((void**)&h16,    g_h16);
    cudaGetSymbolAddress((void**)&obuf,   g_out);
    cudaGetSymbolAddress((void**)&asb,    g_asrc);
    cudaGetSymbolAddress((void**)&adb,    g_adst);
    cudaGetSymbolAddress((void**)&wpad,   g_wpad);
    cudaGetSymbolAddress((void**)&w1tf,   g_w1tf);
    cudaGetSymbolAddress((void**)&w2tf,   g_w2tf);
    cudaGetSymbolAddress((void**)&rowptr, g_rowptr);
    cudaGetSymbolAddress((void**)&wcur,   g_wcur);
    cudaGetSymbolAddress((void**)&csrc,   g_csrc);
    cudaGetSymbolAddress((void**)&bsum,   g_bsum);

    // one-time host-side init (no device allocations)
    static cudaStream_t s2 = nullptr;
    static cudaEvent_t evF = nullptr, evCSR = nullptr;
    if (!s2) {
        cudaStreamCreateWithFlags(&s2, cudaStreamNonBlocking);
        cudaEventCreateWithFlags(&evF,   cudaEventDisableTiming);
        cudaEventCreateWithFlags(&evCSR, cudaEventDisableTiming);
        cudaFuncSetAttribute(mma_gemm_k,
                             cudaFuncAttributeMaxDynamicSharedMemorySize,
                             SMEM_FLOATS * 4);
    }

    const dim3 gMma((N + 127) / 128);
    const dim3 gCls((N + 127) / 128);
    const int  NB = (N + 255) / 256;
    const int  T = E + N;
    const int  gAgg = (N + 7) / 8;
    const int  smb = SMEM_FLOATS * 4;

    // ---- R12 schedule: prep on main; CSR chain on s2 overlapping GEMM1 ----
    prep_k<<<NB, 256>>>(Wc, wpad, W1, w1tf, W2, w2tf, wcur, N);
    cudaEventRecord(evF, 0);
    cudaStreamWaitEvent(s2, evF, 0);

    count_k<<<(E + 255) / 256, 256, 0, s2>>>(ei, E, wcur);
    blocksum_k<<<NB, 256, 0, s2>>>(wcur, bsum, N);
    mma_gemm_k<<<gMma, 512, smb>>>(x, w1tf, h16, asb, adb, as1, ad1, N);
    scan_bsums_k<<<1, NBMAX, 0, s2>>>(bsum, NB);
    scan_final_k<<<NB, 256, 0, s2>>>(wcur, bsum, rowptr, wcur, N);
    fill_k<<<(T + 255) / 256, 256, 0, s2>>>(ei, E, N, wcur, csrc);
    cudaEventRecord(evCSR, s2);
    cudaStreamWaitEvent(0, evCSR, 0);

    agg_k<<<gAgg, 256>>>(rowptr, csrc, h16, asb, adb, b1, obuf, N);

    mma_gemm_k<<<gMma, 512, smb>>>(obuf, w2tf, h16, asb, adb, as2, ad2, N);
    agg_k<<<gAgg, 256>>>(rowptr, csrc, h16, asb, adb, b2, obuf, N);

    gemm_cls_k<<<gCls, 256>>>(obuf, wpad, out, bc, N);
}

// round 17
// speedup vs baseline: 1.1498x; 1.1286x over previous
#include <cuda_runtime.h>
#include <cuda_fp16.h>
#include <cstdint>

#define NN 100000
#define FDIM 128
#define EMAX 1700032
#define NBMAX 512

typedef unsigned long long ull;

// Scratch (device globals — allocation-free per harness rules)
__device__ __half g_h16[NN * FDIM];   // fp16 transformed features (messages)
__device__ float g_out[NN * FDIM];    // aggregated + relu(·+bias) output (fp32)
__device__ float g_asrc[NN * 4];
__device__ float g_adst[NN * 4];
__device__ float g_w1tf[FDIM * FDIM]; // W1^T, tf32-rounded, k pair-interleaved
__device__ float g_w2tf[FDIM * FDIM]; // W2^T, tf32-rounded, k pair-interleaved
__device__ float g_wctf[64 * FDIM];   // Wc^T (64 n x 128 k), tf32, interleaved
__device__ int   g_rowptr[NN + 1];
__device__ int   g_wcur[NN];
__device__ int   g_csrc[EMAX];
__device__ int   g_bsum[NBMAX];

__device__ __forceinline__ uint32_t f2tf(float f) {
    uint32_t r;
    asm("cvt.rna.tf32.f32 %0, %1;" : "=r"(r) : "f"(f));
    return r;
}
#define MMA_TF32(c, a, b) \
    asm volatile("mma.sync.aligned.m16n8k8.row.col.f32.tf32.tf32.f32 " \
        "{%0,%1,%2,%3}, {%4,%5,%6,%7}, {%8,%9}, {%0,%1,%2,%3};" \
        : "+f"((c)[0]), "+f"((c)[1]), "+f"((c)[2]), "+f"((c)[3]) \
        : "r"((a)[0]), "r"((a)[1]), "r"((a)[2]), "r"((a)[3]), \
          "r"((b)[0]), "r"((b)[1]))

__device__ __forceinline__ uint32_t s2u(const void* p) {
    uint32_t a;
    asm("{ .reg .u64 t; cvta.to.shared.u64 t, %1; cvt.u32.u64 %0, t; }"
        : "=r"(a) : "l"(p));
    return a;
}
__device__ __forceinline__ void cpa16(uint32_t dst, const void* src, bool pred) {
    int sz = pred ? 16 : 0;   // src-size 0 -> zero-fill, no read
    asm volatile("cp.async.ca.shared.global [%0], [%1], 16, %2;"
                 :: "r"(dst), "l"(src), "r"(sz));
}
#define CPA_COMMIT() asm volatile("cp.async.commit_group;" ::: "memory")
#define CPA_WAIT(n)  asm volatile("cp.async.wait_group %0;" :: "n"(n) : "memory")

// rna-to-tf32 via bit trick: fp32 is sign-magnitude, so adding 0x1000 and
// letting the tensor core truncate the low 13 bits == cvt.rna.tf32.f32.
#define RNA13(u) ((u) + 0x1000u)

// k pair-interleave map (j-order per k8 group: 0,4,1,5,2,6,3,7)
__host__ __device__ __forceinline__ int kmap(int j) {
    return ((j >> 3) << 3) + ((j >> 1) & 3) + ((j & 1) << 2);
}

// layer-GEMM dynamic smem layout (floats): A stride 36, W stride 40
#define OFF_A0   0
#define OFF_A1   4608        // 128*36
#define OFF_W0   9216
#define OFF_W1   14336       // + 128*40
#define OFF_ATTS 19456
#define OFF_ATTD 19584
#define SMEM_FLOATS 19712    // 78848 bytes

// cls-GEMM dynamic smem layout (floats)
#define COFF_A0  0
#define COFF_A1  4608        // 128*36
#define COFF_W0  9216
#define COFF_W1  11776       // + 64*40
#define CSMEM_FLOATS 14336   // 57344 bytes

// ---------------------------------------------------------------------------
// TF32 tensor GEMM, cp.async double-buffered, fused attention epilogue.
// 512 threads, 16 warps (4M x 4N), warp tile 32x32. (exact R12 version)
// ---------------------------------------------------------------------------
__global__ void __launch_bounds__(512) mma_gemm_k(
    const float* __restrict__ A, const float* __restrict__ WtfT,
    __half* __restrict__ h16,
    float* __restrict__ a_s, float* __restrict__ a_d,
    const float* __restrict__ att_s, const float* __restrict__ att_d, int M)
{
    extern __shared__ float smem[];
    const uint32_t sb = s2u(smem);
    const int tid = threadIdx.x;
    const int lane = tid & 31;
    const int w = tid >> 5;
    const int wm = (w & 3) * 32;
    const int wn = (w >> 2) * 32;      // one head per warp
    const int r0 = blockIdx.x * 128;

    if (tid < 128) {
        smem[OFF_ATTS + tid] = att_s[tid];
        smem[OFF_ATTD + tid] = att_d[tid];
    }

    auto load_slab = [&](int kb, int buf) {
        const uint32_t aB = sb + (buf ? OFF_A1 : OFF_A0) * 4;
        const uint32_t wB = sb + (buf ? OFF_W1 : OFF_W0) * 4;
#pragma unroll
        for (int i = 0; i < 2; i++) {
            int idx = tid + i * 512;
            int row = idx >> 3, cg = idx & 7;
            int g = r0 + row;
            bool ok = g < M;
            cpa16(aB + (row * 36 + cg * 4) * 4,
                  A + (size_t)(ok ? g : 0) * 128 + kb * 32 + cg * 4, ok);
        }
#pragma unroll
        for (int i = 0; i < 2; i++) {
            int idx = tid + i * 512;
            int n = idx >> 3, cg = idx & 7;
            cpa16(wB + (n * 40 + cg * 4) * 4,
                  WtfT + (size_t)n * 128 + kb * 32 + cg * 4, true);
        }
    };

    float acc[2][4][4];
#pragma unroll
    for (int tm = 0; tm < 2; tm++)
#pragma unroll
        for (int tn = 0; tn < 4; tn++)
#pragma unroll
            for (int i = 0; i < 4; i++) acc[tm][tn][i] = 0.f;

    load_slab(0, 0);
    CPA_COMMIT();

#pragma unroll
    for (int kb = 0; kb < 4; kb++) {
        const int buf = kb & 1;
        if (kb < 3) {
            load_slab(kb + 1, buf ^ 1);
            CPA_COMMIT();
            CPA_WAIT(1);
        } else {
            CPA_WAIT(0);
        }
        __syncthreads();

        const float* sA = smem + (buf ? OFF_A1 : OFF_A0);
        const float* sW = smem + (buf ? OFF_W1 : OFF_W0);

#pragma unroll
        for (int k8 = 0; k8 < 4; k8++) {
            const int kq = k8 * 8 + (lane & 3);
            const int rb = wm + (lane >> 2);
            const int nb = wn + (lane >> 2);
            uint32_t a[2][4], b[4][2];
#pragma unroll
            for (int tm = 0; tm < 2; tm++) {
                a[tm][0] = RNA13(__float_as_uint(sA[(rb + tm * 16 + 0) * 36 + kq]));
                a[tm][1] = RNA13(__float_as_uint(sA[(rb + tm * 16 + 8) * 36 + kq]));
                a[tm][2] = RNA13(__float_as_uint(sA[(rb + tm * 16 + 0) * 36 + kq + 4]));
                a[tm][3] = RNA13(__float_as_uint(sA[(rb + tm * 16 + 8) * 36 + kq + 4]));
            }
#pragma unroll
            for (int tn = 0; tn < 4; tn++) {
                float2 bp = *(const float2*)&sW[(nb + tn * 8) * 40 +
                                                k8 * 8 + 2 * (lane & 3)];
                b[tn][0] = __float_as_uint(bp.x);
                b[tn][1] = __float_as_uint(bp.y);
            }
#pragma unroll
            for (int tm = 0; tm < 2; tm++)
#pragma unroll
                for (int tn = 0; tn < 4; tn++)
                    MMA_TF32(acc[tm][tn], a[tm], b[tn]);
        }
        __syncthreads();
    }

    // ---- fused epilogue: fp16 store + attn logits (one head per warp) ----
    const float* satt_s = smem + OFF_ATTS;
    const float* satt_d = smem + OFF_ATTD;
    const int head = wn >> 5;
#pragma unroll
    for (int tm = 0; tm < 2; tm++)
#pragma unroll
        for (int h2 = 0; h2 < 2; h2++) {
            int gr = r0 + wm + tm * 16 + (lane >> 2) + 8 * h2;
            if (gr < M) {
#pragma unroll
                for (int tn = 0; tn < 4; tn++) {
                    __half2 hh = __floats2half2_rn(acc[tm][tn][2 * h2],
                                                   acc[tm][tn][2 * h2 + 1]);
                    *(uint32_t*)(h16 + (size_t)gr * 128 + wn + tn * 8 +
                                 (lane & 3) * 2) = *(uint32_t*)&hh;
                }
            }
            float s0 = 0.f, d0 = 0.f;
#pragma unroll
            for (int tn = 0; tn < 4; tn++) {
                int col = wn + tn * 8 + (lane & 3) * 2;
                float x0 = acc[tm][tn][2 * h2], x1 = acc[tm][tn][2 * h2 + 1];
                s0 += x0 * satt_s[col] + x1 * satt_s[col + 1];
                d0 += x0 * satt_d[col] + x1 * satt_d[col + 1];
            }
#pragma unroll
            for (int off = 1; off <= 2; off <<= 1) {
                s0 += __shfl_xor_sync(0xFFFFFFFF, s0, off);
                d0 += __shfl_xor_sync(0xFFFFFFFF, d0, off);
            }
            if ((lane & 3) == 0 && gr < M) {
                a_s[(size_t)gr * 4 + head] = s0;
                a_d[(size_t)gr * 4 + head] = d0;
            }
        }
}

// ---------------------------------------------------------------------------
// TF32 tensor classifier GEMM: C[M,40] = rna(A) @ Wc + bc.
// 256 threads, 8 warps (4M x 2N), BM=128, BN=64, warp tile 32x32.
// Same pipeline/layout discipline as mma_gemm_k.
// ---------------------------------------------------------------------------
__global__ void __launch_bounds__(256) mma_cls_k(
    const float* __restrict__ A, const float* __restrict__ WcT,
    float* __restrict__ C, const float* __restrict__ bc, int M)
{
    extern __shared__ float smem[];
    const uint32_t sb = s2u(smem);
    const int tid = threadIdx.x;
    const int lane = tid & 31;
    const int w = tid >> 5;
    const int wm = (w & 3) * 32;
    const int wn = (w >> 2) * 32;      // 0 or 32
    const int r0 = blockIdx.x * 128;

    auto load_slab = [&](int kb, int buf) {
        const uint32_t aB = sb + (buf ? COFF_A1 : COFF_A0) * 4;
        const uint32_t wB = sb + (buf ? COFF_W1 : COFF_W0) * 4;
        // A: 128 rows x 8 float4 = 1024; 4 per thread
#pragma unroll
        for (int i = 0; i < 4; i++) {
            int idx = tid + i * 256;
            int row = idx >> 3, cg = idx & 7;
            int g = r0 + row;
            bool ok = g < M;
            cpa16(aB + (row * 36 + cg * 4) * 4,
                  A + (size_t)(ok ? g : 0) * 128 + kb * 32 + cg * 4, ok);
        }
        // Wc^T: 64 n-rows x 8 float4 = 512; 2 per thread
#pragma unroll
        for (int i = 0; i < 2; i++) {
            int idx = tid + i * 256;
            int n = idx >> 3, cg = idx & 7;
            cpa16(wB + (n * 40 + cg * 4) * 4,
                  WcT + (size_t)n * 128 + kb * 32 + cg * 4, true);
        }
    };

    float acc[2][4][4];
#pragma unroll
    for (int tm = 0; tm < 2; tm++)
#pragma unroll
        for (int tn = 0; tn < 4; tn++)
#pragma unroll
            for (int i = 0; i < 4; i++) acc[tm][tn][i] = 0.f;

    load_slab(0, 0);
    CPA_COMMIT();

#pragma unroll
    for (int kb = 0; kb < 4; kb++) {
        const int buf = kb & 1;
        if (kb < 3) {
            load_slab(kb + 1, buf ^ 1);
            CPA_COMMIT();
            CPA_WAIT(1);
        } else {
            CPA_WAIT(0);
        }
        __syncthreads();

        const float* sA = smem + (buf ? COFF_A1 : COFF_A0);
        const float* sW = smem + (buf ? COFF_W1 : COFF_W0);

#pragma unroll
        for (int k8 = 0; k8 < 4; k8++) {
            const int kq = k8 * 8 + (lane & 3);
            const int rb = wm + (lane >> 2);
            const int nb = wn + (lane >> 2);
            uint32_t a[2][4], b[4][2];
#pragma unroll
            for (int tm = 0; tm < 2; tm++) {
                a[tm][0] = RNA13(__float_as_uint(sA[(rb + tm * 16 + 0) * 36 + kq]));
                a[tm][1] = RNA13(__float_as_uint(sA[(rb + tm * 16 + 8) * 36 + kq]));
                a[tm][2] = RNA13(__float_as_uint(sA[(rb + tm * 16 + 0) * 36 + kq + 4]));
                a[tm][3] = RNA13(__float_as_uint(sA[(rb + tm * 16 + 8) * 36 + kq + 4]));
            }
#pragma unroll
            for (int tn = 0; tn < 4; tn++) {
                float2 bp = *(const float2*)&sW[(nb + tn * 8) * 40 +
                                                k8 * 8 + 2 * (lane & 3)];
                b[tn][0] = __float_as_uint(bp.x);
                b[tn][1] = __float_as_uint(bp.y);
            }
#pragma unroll
            for (int tm = 0; tm < 2; tm++)
#pragma unroll
                for (int tn = 0; tn < 4; tn++)
                    MMA_TF32(acc[tm][tn], a[tm], b[tn]);
        }
        __syncthreads();
    }

    // ---- epilogue: fp32 store of cols < 40, + bias ----
#pragma unroll
    for (int tm = 0; tm < 2; tm++)
#pragma unroll
        for (int h2 = 0; h2 < 2; h2++) {
            int gr = r0 + wm + tm * 16 + (lane >> 2) + 8 * h2;
            if (gr < M) {
#pragma unroll
                for (int tn = 0; tn < 4; tn++) {
                    int col = wn + tn * 8 + (lane & 3) * 2;
                    if (col < 40) {
                        float2 v;
                        v.x = acc[tm][tn][2 * h2] + __ldg(bc + col);
                        v.y = acc[tm][tn][2 * h2 + 1] + __ldg(bc + col + 1);
                        *(float2*)(C + (size_t)gr * 40 + col) = v;
                    }
                }
            }
        }
}

// ---------------------------------------------------------------------------
// prep: build W1^T/W2^T/Wc^T tf32-rounded k-pair-interleaved, seed counts
// ---------------------------------------------------------------------------
__global__ void prep_k(const float* __restrict__ wc, float* __restrict__ wctf,
                       const float* __restrict__ w1, float* __restrict__ w1tf,
                       const float* __restrict__ w2, float* __restrict__ w2tf,
                       int* __restrict__ cnt, int N)
{
    int t = blockIdx.x * blockDim.x + threadIdx.x;
    if (t < 128 * 128) {
        int n = t >> 7, j = t & 127;
        int k = kmap(j);
        w1tf[t] = __uint_as_float(f2tf(w1[k * 128 + n]));
        w2tf[t] = __uint_as_float(f2tf(w2[k * 128 + n]));
    }
    if (t < 64 * 128) {
        int n = t >> 7, j = t & 127;
        int k = kmap(j);
        wctf[t] = (n < 40) ? __uint_as_float(f2tf(wc[k * 40 + n])) : 0.f;
    }
    if (t < N) cnt[t] = 1;
}

// ---------------------------------------------------------------------------
// CSR build: count, 3-kernel scan, scatter fill
// ---------------------------------------------------------------------------
__global__ void count_k(const int* __restrict__ ei, int E, int* __restrict__ cnt)
{
    int i = blockIdx.x * blockDim.x + threadIdx.x;
    if (i < E) atomicAdd(cnt + __ldg(ei + E + i), 1);
}

__global__ void blocksum_k(const int* __restrict__ cnt, int* __restrict__ bsum, int N)
{
    __shared__ int s[256];
    int i = blockIdx.x * 256 + threadIdx.x;
    s[threadIdx.x] = (i < N) ? cnt[i] : 0;
    __syncthreads();
#pragma unroll
    for (int st = 128; st > 0; st >>= 1) {
        if (threadIdx.x < st) s[threadIdx.x] += s[threadIdx.x + st];
        __syncthreads();
    }
    if (threadIdx.x == 0) bsum[blockIdx.x] = s[0];
}

__global__ void scan_bsums_k(int* __restrict__ bsum, int NB)
{
    __shared__ int s[NBMAX];
    int t = threadIdx.x;
    int x = (t < NB) ? bsum[t] : 0;
    s[t] = x;
    __syncthreads();
#pragma unroll
    for (int off = 1; off < NBMAX; off <<= 1) {
        int v = (t >= off) ? s[t - off] : 0;
        __syncthreads();
        s[t] += v;
        __syncthreads();
    }
    bsum[t < NBMAX ? t : 0] = s[t] - x;
}

__global__ void scan_final_k(const int* __restrict__ cnt,
                             const int* __restrict__ boff,
                             int* __restrict__ rowptr,
                             int* __restrict__ wcur, int N)
{
    __shared__ int s[256];
    int t = threadIdx.x;
    int i = blockIdx.x * 256 + t;
    int x = (i < N) ? cnt[i] : 0;
    s[t] = x;
    __syncthreads();
#pragma unroll
    for (int off = 1; off < 256; off <<= 1) {
        int v = (t >= off) ? s[t - off] : 0;
        __syncthreads();
        s[t] += v;
        __syncthreads();
    }
    int excl = s[t] - x + boff[blockIdx.x];
    if (i < N) {
        rowptr[i] = excl;
        wcur[i] = excl;
        if (i == N - 1) rowptr[N] = excl + x;
    }
}

__global__ void fill_k(const int* __restrict__ ei, int E, int N,
                       int* __restrict__ wcur, int* __restrict__ csrc)
{
    int t = blockIdx.x * blockDim.x + threadIdx.x;
    int T = E + N;
    if (t >= T) return;
    int s, d;
    if (t < E) { s = __ldg(ei + t); d = __ldg(ei + E + t); }
    else       { s = t - E; d = s; }
    int pos = atomicAdd(wcur + d, 1);
    csrc[pos] = s;
}

// ---------------------------------------------------------------------------
// Aggregation: warp per dst node; two half-warps, 1-deep prefetch each.
// Epilogue applies relu(x*inv + bias).
// ---------------------------------------------------------------------------
__global__ void __launch_bounds__(256) agg_k(
    const int* __restrict__ rowptr, const int* __restrict__ csrc,
    const __half* __restrict__ h16,
    const float* __restrict__ a_s, const float* __restrict__ a_d,
    const float* __restrict__ bias, float* __restrict__ out, int N)
{
    int d = (blockIdx.x * blockDim.x + threadIdx.x) >> 5;
    int lane = threadIdx.x & 31;
    if (d >= N) return;

    const int half = lane >> 4;
    const int sl = lane & 15;
    const int head = sl >> 2;
    int beg = __ldg(rowptr + d);
    int end = __ldg(rowptr + d + 1);
    float ed = __ldg(a_d + 4 * (size_t)d + head);

    float acc[8];
#pragma unroll
    for (int j = 0; j < 8; j++) acc[j] = 0.f;
    float den = 0.f;

    int e = beg + half;
    if (e < end) {
        int s = __ldg(csrc + e);
        float es = __ldg(a_s + 4 * (size_t)s + head);
        uint4 pk = *(const uint4*)(h16 + (size_t)s * 128 + sl * 8);
        for (;;) {
            int e2 = e + 2;
            bool more = e2 < end;
            float esN = 0.f;
            uint4 pkN = make_uint4(0, 0, 0, 0);
            if (more) {
                int sn = __ldg(csrc + e2);
                esN = __ldg(a_s + 4 * (size_t)sn + head);
                pkN = *(const uint4*)(h16 + (size_t)sn * 128 + sl * 8);
            }
            float t = es + ed;
            t = (t > 0.f) ? t : 0.2f * t;
            float p = __expf(t);
            den += p;
            const __half2* hp = (const __half2*)&pk;
#pragma unroll
            for (int j = 0; j < 4; j++) {
                float2 f = __half22float2(hp[j]);
                acc[2 * j] = fmaf(p, f.x, acc[2 * j]);
                acc[2 * j + 1] = fmaf(p, f.y, acc[2 * j + 1]);
            }
            if (!more) break;
            e = e2; es = esN; pk = pkN;
        }
    }

#pragma unroll
    for (int j = 0; j < 8; j++)
        acc[j] += __shfl_down_sync(0xFFFFFFFF, acc[j], 16);
    den += __shfl_down_sync(0xFFFFFFFF, den, 16);

    if (half == 0) {
        float inv = 1.0f / (den + 1e-16f);
        float4 b0 = *(const float4*)(bias + sl * 8);
        float4 b1 = *(const float4*)(bias + sl * 8 + 4);
        float4 v0 = make_float4(fmaxf(fmaf(acc[0], inv, b0.x), 0.f),
                                fmaxf(fmaf(acc[1], inv, b0.y), 0.f),
                                fmaxf(fmaf(acc[2], inv, b0.z), 0.f),
                                fmaxf(fmaf(acc[3], inv, b0.w), 0.f));
        float4 v1 = make_float4(fmaxf(fmaf(acc[4], inv, b1.x), 0.f),
                                fmaxf(fmaf(acc[5], inv, b1.y), 0.f),
                                fmaxf(fmaf(acc[6], inv, b1.z), 0.f),
                                fmaxf(fmaf(acc[7], inv, b1.w), 0.f));
        float4* o = (float4*)(out + (size_t)d * 128 + sl * 8);
        o[0] = v0;
        o[1] = v1;
    }
}

// ---------------------------------------------------------------------------
extern "C" void kernel_launch(void* const* d_in, const int* in_sizes, int n_in,
                              void* d_out, int out_size)
{
    const float* x   = (const float*)d_in[0];
    const int*   ei  = (const int*)  d_in[1];
    const float* W1  = (const float*)d_in[2];
    const float* as1 = (const float*)d_in[3];
    const float* ad1 = (const float*)d_in[4];
    const float* b1  = (const float*)d_in[5];
    const float* W2  = (const float*)d_in[6];
    const float* as2 = (const float*)d_in[7];
    const float* ad2 = (const float*)d_in[8];
    const float* b2  = (const float*)d_in[9];
    const float* Wc  = (const float*)d_in[10];
    const float* bc  = (const float*)d_in[11];
    float* out = (float*)d_out;

    const int N = in_sizes[0] / 128;
    const int E = in_sizes[1] / 2;

    __half* h16;
    float *obuf, *asb, *adb, *wctf, *w1tf, *w2tf;
    int *rowptr, *wcur, *csrc, *bsum;
    cudaGetSymbolAddress((void**)&h16,    g_h16);
    cudaGetSymbolAddress((void**)&obuf,   g_out);
    cudaGetSymbolAddress((void**)&asb,    g_asrc);
    cudaGetSymbolAddress((void**)&adb,    g_adst);
    cudaGetSymbolAddress((void**)&wctf,   g_wctf);
    cudaGetSymbolAddress((void**)&w1tf,   g_w1tf);
    cudaGetSymbolAddress((void**)&w2tf,   g_w2tf);
    cudaGetSymbolAddress((void**)&rowptr, g_rowptr);
    cudaGetSymbolAddress((void**)&wcur,   g_wcur);
    cudaGetSymbolAddress((void**)&csrc,   g_csrc);
    cudaGetSymbolAddress((void**)&bsum,   g_bsum);

    // one-time host-side init (no device allocations)
    static cudaStream_t s2 = nullptr;
    static cudaEvent_t evF = nullptr, evCSR = nullptr;
    if (!s2) {
        cudaStreamCreateWithFlags(&s2, cudaStreamNonBlocking);
        cudaEventCreateWithFlags(&evF,   cudaEventDisableTiming);
        cudaEventCreateWithFlags(&evCSR, cudaEventDisableTiming);
        cudaFuncSetAttribute(mma_gemm_k,
                             cudaFuncAttributeMaxDynamicSharedMemorySize,
                             SMEM_FLOATS * 4);
        cudaFuncSetAttribute(mma_cls_k,
                             cudaFuncAttributeMaxDynamicSharedMemorySize,
                             CSMEM_FLOATS * 4);
    }

    const dim3 gMma((N + 127) / 128);
    const dim3 gCls((N + 127) / 128);
    const int  NB = (N + 255) / 256;
    const int  T = E + N;
    const int  gAgg = (N + 7) / 8;
    const int  smb = SMEM_FLOATS * 4;
    const int  csmb = CSMEM_FLOATS * 4;

    // ---- R12 schedule: prep on main; CSR chain on s2 overlapping GEMM1 ----
    prep_k<<<NB, 256>>>(Wc, wctf, W1, w1tf, W2, w2tf, wcur, N);
    cudaEventRecord(evF, 0);
    cudaStreamWaitEvent(s2, evF, 0);

    count_k<<<(E + 255) / 256, 256, 0, s2>>>(ei, E, wcur);
    blocksum_k<<<NB, 256, 0, s2>>>(wcur, bsum, N);
    mma_gemm_k<<<gMma, 512, smb>>>(x, w1tf, h16, asb, adb, as1, ad1, N);
    scan_bsums_k<<<1, NBMAX, 0, s2>>>(bsum, NB);
    scan_final_k<<<NB, 256, 0, s2>>>(wcur, bsum, rowptr, wcur, N);
    fill_k<<<(T + 255) / 256, 256, 0, s2>>>(ei, E, N, wcur, csrc);
    cudaEventRecord(evCSR, s2);
    cudaStreamWaitEvent(0, evCSR, 0);

    agg_k<<<gAgg, 256>>>(rowptr, csrc, h16, asb, adb, b1, obuf, N);

    mma_gemm_k<<<gMma, 512, smb>>>(obuf, w2tf, h16, asb, adb, as2, ad2, N);
    agg_k<<<gAgg, 256>>>(rowptr, csrc, h16, asb, adb, b2, obuf, N);

    mma_cls_k<<<gCls, 256, csmb>>>(obuf, wctf, out, bc, N);
}